// round 5
// baseline (speedup 1.0000x reference)
#include <cuda_runtime.h>
#include <math.h>

// Problem constants
#define Bsz  64
#define Tlen 256
#define Din  1024
#define Hdim 1024
#define Lnum 4
#define Odim 512
#define NBLK 128   // persistent blocks (<=148 SMs -> all co-resident, spin barrier safe)

// Persistent state (device globals — no allocation allowed).
// h double-buffered by timestep parity: at step t (p=t&1) layers read
// g_h[p][l] (h_{t-1}) and write g_h[p^1][l] (h_t). Layer l>0 reads its input
// from g_h[p^1][l-1], produced earlier in the same timestep (grid barrier).
__device__ float g_h[2][Lnum][Bsz * Hdim];   // 2 MB
__device__ float g_c[Lnum][Bsz * Hdim];      // 1 MB

// Software grid barrier state. g_gen only ever increases (safe across graph
// replays); g_count returns to 0 at the end of every barrier episode.
__device__ volatile unsigned g_gen = 0;
__device__ unsigned g_count = 0;

__device__ __forceinline__ void grid_sync() {
    __syncthreads();
    if (threadIdx.x == 0) {
        __threadfence();
        unsigned my = g_gen;                    // read BEFORE arriving
        if (atomicAdd(&g_count, 1u) == NBLK - 1) {
            g_count = 0;
            __threadfence();
            g_gen = my + 1;                     // release
        } else {
            while (g_gen == my) { __nanosleep(40); }
        }
        __threadfence();
    }
    __syncthreads();
}

union U64 { unsigned long long u; float2 f; };

// Packed fp32x2 FMA (SASS FFMA2) — 2 exact fp32 FMAs per instruction.
__device__ __forceinline__ unsigned long long dup2(float a) {
    unsigned long long r;
    asm("mov.b64 %0, {%1, %1};" : "=l"(r) : "f"(a));
    return r;
}
__device__ __forceinline__ void fma2(unsigned long long &d,
                                     unsigned long long a,
                                     unsigned long long b) {
    asm("fma.rn.f32x2 %0, %1, %2, %0;" : "+l"(d) : "l"(a), "l"(b));
}

__global__ void zero_state() {
    int i = blockIdx.x * blockDim.x + threadIdx.x;
    (&g_h[0][0][0])[i] = 0.f;                 // 2*L*B*H = 524288 floats, exact
    if (i < Lnum * Bsz * Hdim)
        (&g_c[0][0])[i] = 0.f;
}

// Persistent LSTM kernel. 128 blocks x 256 threads.
// Each block owns 8 hidden units (32 gate columns) for ALL (t, layer) steps.
// Warp-group split: threads [0,128) compute the x@Wih^T partial gates,
// threads [128,256) compute h@Whh^T; partials are summed in smem (Gs).
// Each half-thread computes a 4x4 micro-tile of its 64x32 partial.
__global__ __launch_bounds__(256, 1) void lstm_persistent(
    const float* __restrict__ x,
    const float* __restrict__ Wih, const float* __restrict__ Whh,
    const float* __restrict__ bih, const float* __restrict__ bhh)
{
    __shared__ float As[2][32][65];  // [half][k][m], padded (transpose store)
    __shared__ float Ws[2][32][34];  // [half][k][n], padded, 8B-aligned rows
    __shared__ float Gs[64][33];     // gate exchange / partial accumulation
    __shared__ float bias_s[Lnum][32];

    const int tid   = threadIdx.x;
    const int half  = tid >> 7;          // 0: x-phase, 1: h-phase
    const int tid_h = tid & 127;
    const int n0    = blockIdx.x * 8;    // first hidden unit of this block

    // Preload all layers' combined biases (32 gate cols per block, 4 layers)
    if (tid < Lnum * 32) {
        int l = tid >> 5, col = tid & 31;
        int gate = col >> 3, hid = n0 + (col & 7);
        int row  = l * 4 * Hdim + gate * Hdim + hid;
        bias_s[l][col] = bih[row] + bhh[row];
    }

    const int kq  = tid_h & 7;    // float4 chunk within k-tile
    const int mr  = tid_h >> 3;   // 0..15
    const int ty4 = mr * 4;       // output rows ty4..ty4+3
    const int tx4 = kq * 4;       // output cols tx4..tx4+3

    // W rows this thread fetches (tile cols n = mr and mr+16)
    const int nA = mr, nB = mr + 16;
    const int wrow0 = (nA >> 3) * Hdim + n0 + (nA & 7);
    const int wrow1 = (nB >> 3) * Hdim + n0 + (nB & 7);

    __syncthreads();   // bias_s ready

    for (int t = 0; t < Tlen; ++t) {
        const int p = t & 1;
        for (int l = 0; l < Lnum; ++l) {
            // --- per-half operand selection ---
            const float* A; int as; const float* W;
            if (half == 0) {
                if (l == 0) { A = x + (size_t)t * Din; as = Tlen * Din; }
                else        { A = g_h[p ^ 1][l - 1];   as = Hdim; }
                W = Wih + (size_t)l * 4 * Hdim * Din;
            } else {
                A = g_h[p][l]; as = Hdim;
                W = Whh + (size_t)l * 4 * Hdim * Hdim;
            }
            float*       hout = g_h[p ^ 1][l];
            float*       cptr = g_c[l];

            U64 acc[4][2];
            #pragma unroll
            for (int r = 0; r < 4; ++r) {
                acc[r][0].f = make_float2(0.f, 0.f);
                acc[r][1].f = make_float2(0.f, 0.f);
            }

            // Prefetch first k-tile
            float4 pa0 = *(const float4*)(A + (size_t)(mr     ) * as + tx4);
            float4 pa1 = *(const float4*)(A + (size_t)(mr + 16) * as + tx4);
            float4 pa2 = *(const float4*)(A + (size_t)(mr + 32) * as + tx4);
            float4 pa3 = *(const float4*)(A + (size_t)(mr + 48) * as + tx4);
            float4 pw0 = *(const float4*)(W + (size_t)wrow0 * 1024 + tx4);
            float4 pw1 = *(const float4*)(W + (size_t)wrow1 * 1024 + tx4);

            for (int k0 = 0; k0 < 1024; k0 += 32) {
                __syncthreads();
                As[half][tx4 + 0][mr     ] = pa0.x; As[half][tx4 + 1][mr     ] = pa0.y;
                As[half][tx4 + 2][mr     ] = pa0.z; As[half][tx4 + 3][mr     ] = pa0.w;
                As[half][tx4 + 0][mr + 16] = pa1.x; As[half][tx4 + 1][mr + 16] = pa1.y;
                As[half][tx4 + 2][mr + 16] = pa1.z; As[half][tx4 + 3][mr + 16] = pa1.w;
                As[half][tx4 + 0][mr + 32] = pa2.x; As[half][tx4 + 1][mr + 32] = pa2.y;
                As[half][tx4 + 2][mr + 32] = pa2.z; As[half][tx4 + 3][mr + 32] = pa2.w;
                As[half][tx4 + 0][mr + 48] = pa3.x; As[half][tx4 + 1][mr + 48] = pa3.y;
                As[half][tx4 + 2][mr + 48] = pa3.z; As[half][tx4 + 3][mr + 48] = pa3.w;
                Ws[half][tx4 + 0][nA] = pw0.x; Ws[half][tx4 + 1][nA] = pw0.y;
                Ws[half][tx4 + 2][nA] = pw0.z; Ws[half][tx4 + 3][nA] = pw0.w;
                Ws[half][tx4 + 0][nB] = pw1.x; Ws[half][tx4 + 1][nB] = pw1.y;
                Ws[half][tx4 + 2][nB] = pw1.z; Ws[half][tx4 + 3][nB] = pw1.w;
                __syncthreads();

                // Prefetch next k-tile while computing this one
                int k1 = k0 + 32;
                if (k1 < 1024) {
                    pa0 = *(const float4*)(A + (size_t)(mr     ) * as + k1 + tx4);
                    pa1 = *(const float4*)(A + (size_t)(mr + 16) * as + k1 + tx4);
                    pa2 = *(const float4*)(A + (size_t)(mr + 32) * as + k1 + tx4);
                    pa3 = *(const float4*)(A + (size_t)(mr + 48) * as + k1 + tx4);
                    pw0 = *(const float4*)(W + (size_t)wrow0 * 1024 + k1 + tx4);
                    pw1 = *(const float4*)(W + (size_t)wrow1 * 1024 + k1 + tx4);
                }

                #pragma unroll
                for (int k = 0; k < 32; ++k) {
                    unsigned long long b0 =
                        *(const unsigned long long*)&Ws[half][k][tx4];
                    unsigned long long b1 =
                        *(const unsigned long long*)&Ws[half][k][tx4 + 2];
                    float a0 = As[half][k][ty4 + 0], a1 = As[half][k][ty4 + 1];
                    float a2 = As[half][k][ty4 + 2], a3 = As[half][k][ty4 + 3];
                    unsigned long long A0 = dup2(a0), A1 = dup2(a1);
                    unsigned long long A2 = dup2(a2), A3 = dup2(a3);
                    fma2(acc[0][0].u, A0, b0); fma2(acc[0][1].u, A0, b1);
                    fma2(acc[1][0].u, A1, b0); fma2(acc[1][1].u, A1, b1);
                    fma2(acc[2][0].u, A2, b0); fma2(acc[2][1].u, A2, b1);
                    fma2(acc[3][0].u, A3, b0); fma2(acc[3][1].u, A3, b1);
                }
            }

            // Combine the two halves' partial gates in smem
            if (half == 0) {
                #pragma unroll
                for (int r = 0; r < 4; ++r) {
                    Gs[ty4 + r][tx4 + 0] = acc[r][0].f.x;
                    Gs[ty4 + r][tx4 + 1] = acc[r][0].f.y;
                    Gs[ty4 + r][tx4 + 2] = acc[r][1].f.x;
                    Gs[ty4 + r][tx4 + 3] = acc[r][1].f.y;
                }
            }
            __syncthreads();
            if (half == 1) {
                #pragma unroll
                for (int r = 0; r < 4; ++r) {
                    Gs[ty4 + r][tx4 + 0] += acc[r][0].f.x;
                    Gs[ty4 + r][tx4 + 1] += acc[r][0].f.y;
                    Gs[ty4 + r][tx4 + 2] += acc[r][1].f.x;
                    Gs[ty4 + r][tx4 + 3] += acc[r][1].f.y;
                }
            }
            __syncthreads();

            // Pointwise LSTM update: 64 rows x 8 hidden = 512 elems, 2/thread
            #pragma unroll
            for (int q = 0; q < 2; ++q) {
                int idx = tid * 2 + q;        // 0..511
                int m = idx >> 3, hl = idx & 7;
                float gi = Gs[m][hl]      + bias_s[l][hl];
                float gf = Gs[m][8  + hl] + bias_s[l][8  + hl];
                float gg = Gs[m][16 + hl] + bias_s[l][16 + hl];
                float go = Gs[m][24 + hl] + bias_s[l][24 + hl];
                float ig = 1.f / (1.f + expf(-gi));
                float fg = 1.f / (1.f + expf(-gf));
                float gt = tanhf(gg);
                float og = 1.f / (1.f + expf(-go));
                int off = m * Hdim + n0 + hl;
                float cn = fg * cptr[off] + ig * gt;
                cptr[off] = cn;
                hout[off] = og * tanhf(cn);
            }

            grid_sync();   // publish h_t[l] / c[l] to all blocks
        }
    }
}

// out[b][o] = h_last[b] . W_fc[o] + b_fc[o]. One warp per output element.
// Final h lives in g_h[0][L-1] (t=255 has parity 1, writes buffer 0).
__global__ void fc_kernel(const float* __restrict__ Wfc,
                          const float* __restrict__ bfc,
                          float* __restrict__ out)
{
    const float* h = g_h[0][Lnum - 1];
    int warp = (blockIdx.x * blockDim.x + threadIdx.x) >> 5;
    int lane = threadIdx.x & 31;
    int b = warp >> 9;          // / 512
    int o = warp & (Odim - 1);
    const float4* hv = (const float4*)(h   + (size_t)b * Hdim);
    const float4* wv = (const float4*)(Wfc + (size_t)o * Hdim);
    float s = 0.f;
    #pragma unroll
    for (int it = 0; it < 8; ++it) {
        float4 a = hv[it * 32 + lane];
        float4 w = wv[it * 32 + lane];
        s += a.x * w.x + a.y * w.y + a.z * w.z + a.w * w.w;
    }
    #pragma unroll
    for (int off = 16; off; off >>= 1)
        s += __shfl_xor_sync(0xffffffffu, s, off);
    if (lane == 0)
        out[(size_t)b * Odim + o] = s + bfc[o];
}

extern "C" void kernel_launch(void* const* d_in, const int* in_sizes, int n_in,
                              void* d_out, int out_size)
{
    const float* x   = (const float*)d_in[0];
    const float* Wih = (const float*)d_in[1];
    const float* Whh = (const float*)d_in[2];
    const float* bih = (const float*)d_in[3];
    const float* bhh = (const float*)d_in[4];
    const float* Wfc = (const float*)d_in[5];
    const float* bfc = (const float*)d_in[6];
    float* out = (float*)d_out;

    zero_state<<<512, 1024>>>();
    lstm_persistent<<<NBLK, 256>>>(x, Wih, Whh, bih, bhh);
    fc_kernel<<<(Bsz * Odim) / 8, 256>>>(Wfc, bfc, out);   // 4096 blocks
}

// round 7
// speedup vs baseline: 1.1318x; 1.1318x over previous
#include <cuda_runtime.h>
#include <cuda_bf16.h>
#include <stdint.h>
#include <math.h>

#define Bsz  64
#define Tlen 256
#define Hdim 1024
#define Lnum 4
#define Odim 512
#define NBLK 64
#define NCHUNK 16
#define ASTR 272            // smem row pitch bytes (128 bf16 = 256B + 16 pad)
#define TILE_HALF 17408     // 64 rows * 272B
#define TILE_BOTH 34816     // hi + lo

// ---- persistent device state ----
__device__ float g_h[2][Lnum][Bsz * Hdim];
__device__ float g_c[Lnum][Bsz * Hdim];
// pre-split weights: per (l, nb, ck) a 64x128 bf16 tile, row-major (n-row, k contig)
__device__ __align__(16) char g_Whi[(size_t)Lnum * 64 * 16 * 16384];
__device__ __align__(16) char g_Wlo[(size_t)Lnum * 64 * 16 * 16384];

__device__ volatile unsigned g_gen = 0;
__device__ unsigned g_count = 0;

__device__ __forceinline__ void grid_sync() {
    __syncthreads();
    if (threadIdx.x == 0) {
        __threadfence();
        unsigned my = g_gen;
        if (atomicAdd(&g_count, 1u) == NBLK - 1) {
            g_count = 0; __threadfence(); g_gen = my + 1;
        } else {
            while (g_gen == my) { __nanosleep(40); }
        }
        __threadfence();
    }
    __syncthreads();
}

__device__ __forceinline__ uint32_t smem_u32(const void* p) {
    uint32_t a;
    asm("{ .reg .u64 t; cvta.to.shared.u64 t, %1; cvt.u32.u64 %0, t; }"
        : "=r"(a) : "l"(p));
    return a;
}
__device__ __forceinline__ float ex2f(float x) {
    float r; asm("ex2.approx.f32 %0, %1;" : "=f"(r) : "f"(x)); return r;
}
__device__ __forceinline__ float rcpf(float x) {
    float r; asm("rcp.approx.f32 %0, %1;" : "=f"(r) : "f"(x)); return r;
}
__device__ __forceinline__ float sigf(float x) {
    return rcpf(1.0f + ex2f(-1.4426950408889634f * x));
}
__device__ __forceinline__ float tanhfast(float x) {
    float e = ex2f(2.8853900817779268f * x);   // exp(2x)
    return 1.0f - 2.0f * rcpf(e + 1.0f);
}

#define LDSM4(r, a)                                                           \
    asm volatile("ldmatrix.sync.aligned.m8n8.x4.shared.b16 {%0,%1,%2,%3}, [%4];" \
        : "=r"((r)[0]), "=r"((r)[1]), "=r"((r)[2]), "=r"((r)[3]) : "r"(a))

#define MMA(d, a, b0, b1)                                                     \
    asm volatile("mma.sync.aligned.m16n8k16.row.col.f32.bf16.bf16.f32 "       \
        "{%0,%1,%2,%3},{%4,%5,%6,%7},{%8,%9},{%0,%1,%2,%3};"                  \
        : "+f"((d)[0]), "+f"((d)[1]), "+f"((d)[2]), "+f"((d)[3])              \
        : "r"((a)[0]), "r"((a)[1]), "r"((a)[2]), "r"((a)[3]),                 \
          "r"(b0), "r"(b1))

#define CPA16(dst, src) \
    asm volatile("cp.async.ca.shared.global [%0], [%1], 16;" :: "r"(dst), "l"(src))
#define CPA_COMMIT() asm volatile("cp.async.commit_group;" ::: "memory")
#define CPA_WAIT(n)  asm volatile("cp.async.wait_group %0;" :: "n"(n) : "memory")

// smem layout: bias[4][64] | A (2 buf x hi/lo) | W (2 buf x hi/lo)
#define OFF_BIAS 0
#define OFF_A    1024
#define OFF_W    (1024 + 2 * TILE_BOTH)
#define SMEM_DYN (OFF_W + 2 * TILE_BOTH)

__global__ void zero_state() {
    int i = blockIdx.x * blockDim.x + threadIdx.x;
    (&g_h[0][0][0])[i] = 0.f;                 // 524288 exact
    if (i < Lnum * Bsz * Hdim)
        (&g_c[0][0])[i] = 0.f;
}

// split weights to bf16 hi/lo, row-major 64x128 tiles
__global__ void prep_weights(const float* __restrict__ Wih,
                             const float* __restrict__ Whh) {
    size_t idx = (size_t)blockIdx.x * 1024 + threadIdx.x;   // 2^25
    int c  = (int)(idx & 127);
    int n  = (int)((idx >> 7) & 63);
    int ck = (int)((idx >> 13) & 15);
    int nb = (int)((idx >> 17) & 63);
    int l  = (int)(idx >> 23);
    int gate = n >> 4, hid = nb * 16 + (n & 15);
    int kk = ck * 128 + c;
    size_t grow = (size_t)l * 4096 * 1024 + (size_t)(gate * 1024 + hid) * 1024;
    float v = (kk < 1024) ? Wih[grow + kk] : Whh[grow + kk - 1024];
    __nv_bfloat16 h = __float2bfloat16(v);
    __nv_bfloat16 lo = __float2bfloat16(v - __bfloat162float(h));
    size_t tile = ((((size_t)l * 64 + nb) * 16) + ck) * 16384;
    size_t off  = (size_t)n * 256 + (size_t)c * 2;
    *(__nv_bfloat16*)(g_Whi + tile + off) = h;
    *(__nv_bfloat16*)(g_Wlo + tile + off) = lo;
}

__global__ __launch_bounds__(256, 1) void lstm_persistent(
    const float* __restrict__ x,
    const float* __restrict__ bih, const float* __restrict__ bhh)
{
    extern __shared__ char sm[];
    const uint32_t sbase = smem_u32(sm);

    const int tid  = threadIdx.x;
    const int wid  = tid >> 5;
    const int lane = tid & 31;
    const int n0   = blockIdx.x * 16;     // first hidden unit of block
    const int warpM = (wid & 3) * 16;     // 16 batch rows
    const int warpN = (wid >> 2) * 32;    // 32 gate cols

    {   // combined bias [layer][64], col = gate*16 + hid_local
        int li = tid >> 6, col = tid & 63;
        int gate = col >> 4, hid = n0 + (col & 15);
        int row = li * 4096 + gate * 1024 + hid;
        ((float*)(sm + OFF_BIAS))[li * 64 + col] = bih[row] + bhh[row];
    }
    __syncthreads();

    // ldmatrix per-lane byte offsets (within a hi or lo half-tile)
    const uint32_t a_off = (uint32_t)(warpM + (lane & 15)) * ASTR
                         + ((uint32_t)(lane >> 4) << 4);          // +8 cols
    uint32_t b_off[2];
    #pragma unroll
    for (int p = 0; p < 2; ++p)
        b_off[p] = (uint32_t)(warpN + p * 16 + ((lane >> 4) << 3) + (lane & 7)) * ASTR
                 + (((uint32_t)(lane >> 3) & 1u) << 4);

    // A convert assignment: row = tid>>2, col segment (tid&3)*32
    const int arow = tid >> 2;
    const int aseg = (tid & 3) * 32;

    for (int t = 0; t < Tlen; ++t) {
        const int p = t & 1;
        for (int l = 0; l < Lnum; ++l) {
            const float* inb; size_t instr_;
            if (l == 0) { inb = x + (size_t)t * 1024; instr_ = (size_t)Tlen * 1024; }
            else        { inb = g_h[p ^ 1][l - 1];    instr_ = 1024; }
            const float* hprev = g_h[p][l];

            float acc[4][4];
            #pragma unroll
            for (int j = 0; j < 4; ++j)
                acc[j][0] = acc[j][1] = acc[j][2] = acc[j][3] = 0.f;

            // pre-issue W chunk 0 -> buf 0
            {
                size_t toff = ((((size_t)l * 64 + blockIdx.x) * 16) + 0) * 16384;
                uint32_t dhi = sbase + OFF_W, dlo = dhi + TILE_HALF;
                #pragma unroll
                for (int i = 0; i < 4; ++i) {
                    int u = i * 256 + tid;
                    uint32_t d = (uint32_t)(u >> 4) * ASTR + (uint32_t)(u & 15) * 16;
                    CPA16(dhi + d, g_Whi + toff + (size_t)u * 16);
                    CPA16(dlo + d, g_Wlo + toff + (size_t)u * 16);
                }
                CPA_COMMIT();
            }

            for (int ck = 0; ck < NCHUNK; ++ck) {
                const int buf = ck & 1;
                const uint32_t aHi = sbase + OFF_A + (uint32_t)buf * TILE_BOTH;
                const uint32_t aLo = aHi + TILE_HALF;
                const uint32_t wHi = sbase + OFF_W + (uint32_t)buf * TILE_BOTH;
                const uint32_t wLo = wHi + TILE_HALF;

                // 1. convert A chunk (64 x 128) fp32 -> bf16 hi/lo into buf
                {
                    const float* src; size_t rs;
                    if (ck < 8) { src = inb + (size_t)ck * 128;         rs = instr_; }
                    else        { src = hprev + (size_t)(ck - 8) * 128; rs = 1024;  }
                    const float* s = src + (size_t)arow * rs + aseg;
                    uint32_t hiw[16], low[16];
                    #pragma unroll
                    for (int i = 0; i < 8; ++i) {
                        float4 v = *(const float4*)(s + i * 4);
                        __nv_bfloat16 h0 = __float2bfloat16(v.x);
                        __nv_bfloat16 h1 = __float2bfloat16(v.y);
                        __nv_bfloat16 h2 = __float2bfloat16(v.z);
                        __nv_bfloat16 h3 = __float2bfloat16(v.w);
                        union { __nv_bfloat162 b; uint32_t u; } q;
                        q.b = __halves2bfloat162(h0, h1); hiw[i*2]   = q.u;
                        q.b = __halves2bfloat162(h2, h3); hiw[i*2+1] = q.u;
                        q.b = __halves2bfloat162(
                            __float2bfloat16(v.x - __bfloat162float(h0)),
                            __float2bfloat16(v.y - __bfloat162float(h1)));
                        low[i*2] = q.u;
                        q.b = __halves2bfloat162(
                            __float2bfloat16(v.z - __bfloat162float(h2)),
                            __float2bfloat16(v.w - __bfloat162float(h3)));
                        low[i*2+1] = q.u;
                    }
                    uint32_t dst = aHi + (uint32_t)arow * ASTR + (uint32_t)aseg * 2;
                    #pragma unroll
                    for (int i = 0; i < 4; ++i)
                        asm volatile("st.shared.v4.u32 [%0], {%1,%2,%3,%4};"
                            :: "r"(dst + i * 16), "r"(hiw[i*4]), "r"(hiw[i*4+1]),
                               "r"(hiw[i*4+2]), "r"(hiw[i*4+3]));
                    dst = aLo + (uint32_t)arow * ASTR + (uint32_t)aseg * 2;
                    #pragma unroll
                    for (int i = 0; i < 4; ++i)
                        asm volatile("st.shared.v4.u32 [%0], {%1,%2,%3,%4};"
                            :: "r"(dst + i * 16), "r"(low[i*4]), "r"(low[i*4+1]),
                               "r"(low[i*4+2]), "r"(low[i*4+3]));
                }

                __syncthreads();   // all warps done with MMA(ck-1) -> W[buf^1] free

                // 2. prefetch W chunk ck+1 into other buffer
                if (ck + 1 < NCHUNK) {
                    size_t toff = ((((size_t)l * 64 + blockIdx.x) * 16) + ck + 1) * 16384;
                    uint32_t dhi = sbase + OFF_W + (uint32_t)(buf ^ 1) * TILE_BOTH;
                    uint32_t dlo = dhi + TILE_HALF;
                    #pragma unroll
                    for (int i = 0; i < 4; ++i) {
                        int u = i * 256 + tid;
                        uint32_t d = (uint32_t)(u >> 4) * ASTR + (uint32_t)(u & 15) * 16;
                        CPA16(dhi + d, g_Whi + toff + (size_t)u * 16);
                        CPA16(dlo + d, g_Wlo + toff + (size_t)u * 16);
                    }
                    CPA_COMMIT();
                    CPA_WAIT(1);   // W[buf] (chunk ck) has landed
                } else {
                    CPA_WAIT(0);
                }
                __syncthreads();   // A[buf] + W[buf] visible to all

                // 3. MMAs: 8 k-steps x (4 n-tiles x 3 passes)
                #pragma unroll
                for (int k = 0; k < 8; ++k) {
                    const uint32_t kb = (uint32_t)k * 32;   // 16 bf16 = 32B
                    uint32_t ah[4], al[4], bh0[4], bh1[4], bl0[4], bl1[4];
                    LDSM4(ah,  aHi + a_off + kb);
                    LDSM4(al,  aLo + a_off + kb);
                    LDSM4(bh0, wHi + b_off[0] + kb);
                    LDSM4(bh1, wHi + b_off[1] + kb);
                    LDSM4(bl0, wLo + b_off[0] + kb);
                    LDSM4(bl1, wLo + b_off[1] + kb);
                    MMA(acc[0], ah, bh0[0], bh0[1]);
                    MMA(acc[1], ah, bh0[2], bh0[3]);
                    MMA(acc[2], ah, bh1[0], bh1[1]);
                    MMA(acc[3], ah, bh1[2], bh1[3]);
                    MMA(acc[0], al, bh0[0], bh0[1]);
                    MMA(acc[1], al, bh0[2], bh0[3]);
                    MMA(acc[2], al, bh1[0], bh1[1]);
                    MMA(acc[3], al, bh1[2], bh1[3]);
                    MMA(acc[0], ah, bl0[0], bl0[1]);
                    MMA(acc[1], ah, bl0[2], bl0[3]);
                    MMA(acc[2], ah, bl1[0], bl1[1]);
                    MMA(acc[3], ah, bl1[2], bl1[3]);
                }
            }

            // epilogue: gates -> smem (reuse A buf0 region), pointwise, store
            float* Gs = (float*)(sm + OFF_A);   // stride 65 floats
            #pragma unroll
            for (int j = 0; j < 4; ++j) {
                int cb = warpN + j * 8 + (lane & 3) * 2;
                int r0 = warpM + (lane >> 2);
                Gs[r0 * 65 + cb]       = acc[j][0];
                Gs[r0 * 65 + cb + 1]   = acc[j][1];
                Gs[(r0+8) * 65 + cb]   = acc[j][2];
                Gs[(r0+8) * 65 + cb+1] = acc[j][3];
            }
            __syncthreads();

            const float* bias = (const float*)(sm + OFF_BIAS) + l * 64;
            float* hout = g_h[p ^ 1][l];
            float* cpt  = g_c[l];
            #pragma unroll
            for (int q = 0; q < 4; ++q) {
                int e = tid + 256 * q;            // 0..1023
                int b = e >> 4, hl = e & 15;
                float gi = Gs[b * 65 + hl]      + bias[hl];
                float gf = Gs[b * 65 + 16 + hl] + bias[16 + hl];
                float gg = Gs[b * 65 + 32 + hl] + bias[32 + hl];
                float go = Gs[b * 65 + 48 + hl] + bias[48 + hl];
                float ig = sigf(gi), fg = sigf(gf), og = sigf(go);
                float gt = tanhfast(gg);
                int o = b * 1024 + n0 + hl;
                float cn = fg * cpt[o] + ig * gt;
                cpt[o]  = cn;
                hout[o] = og * tanhfast(cn);
            }

            grid_sync();   // publish h/c; also guards Gs region reuse
        }
    }
}

__global__ void fc_kernel(const float* __restrict__ Wfc,
                          const float* __restrict__ bfc,
                          float* __restrict__ out)
{
    const float* h = g_h[0][Lnum - 1];   // t=255 (p=1) wrote buffer 0
    int warp = (blockIdx.x * blockDim.x + threadIdx.x) >> 5;
    int lane = threadIdx.x & 31;
    int b = warp >> 9;
    int o = warp & (Odim - 1);
    const float4* hv = (const float4*)(h   + (size_t)b * Hdim);
    const float4* wv = (const float4*)(Wfc + (size_t)o * Hdim);
    float s = 0.f;
    #pragma unroll
    for (int it = 0; it < 8; ++it) {
        float4 a = hv[it * 32 + lane];
        float4 w = wv[it * 32 + lane];
        s += a.x * w.x + a.y * w.y + a.z * w.z + a.w * w.w;
    }
    #pragma unroll
    for (int off = 16; off; off >>= 1)
        s += __shfl_xor_sync(0xffffffffu, s, off);
    if (lane == 0)
        out[(size_t)b * Odim + o] = s + bfc[o];
}

extern "C" void kernel_launch(void* const* d_in, const int* in_sizes, int n_in,
                              void* d_out, int out_size)
{
    const float* x   = (const float*)d_in[0];
    const float* Wih = (const float*)d_in[1];
    const float* Whh = (const float*)d_in[2];
    const float* bih = (const float*)d_in[3];
    const float* bhh = (const float*)d_in[4];
    const float* Wfc = (const float*)d_in[5];
    const float* bfc = (const float*)d_in[6];
    float* out = (float*)d_out;

    cudaFuncSetAttribute(lstm_persistent,
                         cudaFuncAttributeMaxDynamicSharedMemorySize, SMEM_DYN);

    zero_state<<<512, 1024>>>();
    prep_weights<<<32768, 1024>>>(Wih, Whh);
    lstm_persistent<<<NBLK, 256, SMEM_DYN>>>(x, bih, bhh);
    fc_kernel<<<(Bsz * Odim) / 8, 256>>>(Wfc, bfc, out);
}

// round 8
// speedup vs baseline: 1.9801x; 1.7496x over previous
#include <cuda_runtime.h>
#include <cuda_bf16.h>
#include <stdint.h>
#include <math.h>

#define Bsz  64
#define Tlen 256
#define Hdim 1024
#define Lnum 4
#define Odim 512
#define NBLK 128
#define NTHR 512
#define NCHUNK 16
#define ASTR 272              // smem row pitch (256B row + 16B pad)

// ---- persistent device state ----
// weights pre-split: per (l, nb, ck) a 32x128 bf16 tile, row-major
__device__ __nv_bfloat16 g_Whi[(size_t)Lnum * 128 * 16 * 32 * 128];  // 64 MB
__device__ __nv_bfloat16 g_Wlo[(size_t)Lnum * 128 * 16 * 32 * 128];  // 64 MB
// x pre-split: per (t, ck) a 64x128 tile
__device__ __nv_bfloat16 g_xb_hi[(size_t)Tlen * 8 * 64 * 128];       // 32 MB
__device__ __nv_bfloat16 g_xb_lo[(size_t)Tlen * 8 * 64 * 128];       // 32 MB
// h as hi/lo tiles: [parity][l][ck 8][row 64][col 128]
__device__ __nv_bfloat16 g_hb_hi[2 * Lnum * 8 * 64 * 128];           // 1 MB
__device__ __nv_bfloat16 g_hb_lo[2 * Lnum * 8 * 64 * 128];           // 1 MB
__device__ float g_hfin[Bsz * Hdim];     // final h for FC

__device__ volatile unsigned g_gen = 0;
__device__ unsigned g_count = 0;

__device__ __forceinline__ void grid_sync() {
    __syncthreads();
    if (threadIdx.x == 0) {
        __threadfence();
        unsigned my = g_gen;
        if (atomicAdd(&g_count, 1u) == NBLK - 1) {
            g_count = 0; __threadfence(); g_gen = my + 1;
        } else {
            while (g_gen == my) { __nanosleep(40); }
        }
        __threadfence();   // fence.sc.gpu -> L1 invalidate (CCTL.IVALL)
    }
    __syncthreads();
}

__device__ __forceinline__ uint32_t smem_u32(const void* p) {
    uint32_t a;
    asm("{ .reg .u64 t; cvta.to.shared.u64 t, %1; cvt.u32.u64 %0, t; }"
        : "=r"(a) : "l"(p));
    return a;
}
__device__ __forceinline__ float ex2f(float x) {
    float r; asm("ex2.approx.f32 %0, %1;" : "=f"(r) : "f"(x)); return r;
}
__device__ __forceinline__ float rcpf(float x) {
    float r; asm("rcp.approx.f32 %0, %1;" : "=f"(r) : "f"(x)); return r;
}
__device__ __forceinline__ float sigf(float x) {
    return rcpf(1.0f + ex2f(-1.4426950408889634f * x));
}
__device__ __forceinline__ float tanhfast(float x) {
    float e = ex2f(2.8853900817779268f * x);
    return 1.0f - 2.0f * rcpf(e + 1.0f);
}

#define LDSM4(r, a)                                                           \
    asm volatile("ldmatrix.sync.aligned.m8n8.x4.shared.b16 {%0,%1,%2,%3}, [%4];" \
        : "=r"((r)[0]), "=r"((r)[1]), "=r"((r)[2]), "=r"((r)[3]) : "r"(a))
#define LDSM2(r, a)                                                           \
    asm volatile("ldmatrix.sync.aligned.m8n8.x2.shared.b16 {%0,%1}, [%2];"    \
        : "=r"((r)[0]), "=r"((r)[1]) : "r"(a))

#define MMA(d, a, b0, b1)                                                     \
    asm volatile("mma.sync.aligned.m16n8k16.row.col.f32.bf16.bf16.f32 "       \
        "{%0,%1,%2,%3},{%4,%5,%6,%7},{%8,%9},{%0,%1,%2,%3};"                  \
        : "+f"((d)[0]), "+f"((d)[1]), "+f"((d)[2]), "+f"((d)[3])              \
        : "r"((a)[0]), "r"((a)[1]), "r"((a)[2]), "r"((a)[3]),                 \
          "r"(b0), "r"(b1))

#define CPA16(dst, src) \
    asm volatile("cp.async.ca.shared.global [%0], [%1], 16;" :: "r"(dst), "l"(src))
#define CPA_COMMIT() asm volatile("cp.async.commit_group;" ::: "memory")
#define CPA_WAIT(n)  asm volatile("cp.async.wait_group %0;" :: "n"(n) : "memory")

// smem layout
#define OFF_BIAS 0                       // [4][32] f32 = 512 B
#define OFF_C    512                     // [4][64][8] f32 = 8192 B
#define OFF_A    8704                    // 2 buf x (hi 17408 + lo 17408)
#define OFF_W    (8704 + 69632)          // 2 buf x (hi 8704 + lo 8704)
#define SMEM_DYN (OFF_W + 34816)         // 113152

__global__ void zero_hb() {              // zero parity-0 h tiles (h0 = 0)
    int i = blockIdx.x * 1024 + threadIdx.x;     // grid 256 -> 262144
    g_hb_hi[i] = __float2bfloat16(0.f);
    g_hb_lo[i] = __float2bfloat16(0.f);
}

__global__ void prep_x(const float* __restrict__ x) {
    size_t idx = (size_t)blockIdx.x * 1024 + threadIdx.x;   // 2^24
    int c  = (int)(idx & 127);
    int b  = (int)((idx >> 7) & 63);
    int ck = (int)((idx >> 13) & 7);
    int t  = (int)(idx >> 16);
    float v = x[((size_t)b * Tlen + t) * 1024 + ck * 128 + c];
    __nv_bfloat16 h = __float2bfloat16(v);
    size_t dst = (((size_t)(t * 8 + ck)) * 64 + b) * 128 + c;
    g_xb_hi[dst] = h;
    g_xb_lo[dst] = __float2bfloat16(v - __bfloat162float(h));
}

__global__ void prep_weights(const float* __restrict__ Wih,
                             const float* __restrict__ Whh) {
    size_t idx = (size_t)blockIdx.x * 1024 + threadIdx.x;   // 2^25
    int c  = (int)(idx & 127);
    int n  = (int)((idx >> 7) & 31);
    int ck = (int)((idx >> 12) & 15);
    int nb = (int)((idx >> 16) & 127);
    int l  = (int)(idx >> 23);
    int gate = n >> 3, hid = nb * 8 + (n & 7);
    int kk = ck * 128 + c;
    size_t grow = (size_t)l * 4096 * 1024 + (size_t)(gate * 1024 + hid) * 1024;
    float v = (kk < 1024) ? Wih[grow + kk] : Whh[grow + kk - 1024];
    __nv_bfloat16 h = __float2bfloat16(v);
    size_t e = ((((size_t)l * 128 + nb) * 16) + ck) * 4096 + (size_t)n * 128 + c;
    g_Whi[e] = h;
    g_Wlo[e] = __float2bfloat16(v - __bfloat162float(h));
}

__global__ __launch_bounds__(NTHR, 1) void lstm_persistent(
    const float* __restrict__ bih, const float* __restrict__ bhh)
{
    extern __shared__ char sm[];
    const uint32_t sbase = smem_u32(sm);

    const int tid  = threadIdx.x;
    const int wid  = tid >> 5;
    const int lane = tid & 31;
    const int bx   = blockIdx.x;
    const int n0   = bx * 8;                 // first hidden unit of block
    const int warpM = (wid & 3) * 16;        // 16 batch rows
    const int warpN = (wid >> 2) * 8;        // 8 gate cols (one gate)

    if (tid < Lnum * 32) {   // combined bias [l][32], col = gate*8 + hidlocal
        int li = tid >> 5, col = tid & 31;
        int gate = col >> 3, hid = n0 + (col & 7);
        int row = li * 4096 + gate * 1024 + hid;
        ((float*)(sm + OFF_BIAS))[li * 32 + col] = bih[row] + bhh[row];
    }
    float* csm = (float*)(sm + OFF_C);       // [4][64][8]
    #pragma unroll
    for (int i = 0; i < 4; ++i)
        csm[i * NTHR + tid] = 0.f;
    __syncthreads();

    // ldmatrix per-lane offsets
    const uint32_t a_off = (uint32_t)(warpM + (lane & 15)) * ASTR
                         + ((uint32_t)(lane >> 4) << 4);
    const uint32_t b_off = (uint32_t)(warpN + (lane & 7)) * ASTR
                         + (((uint32_t)(lane >> 3) & 1u) << 4);
    // cp.async per-thread dest offsets
    const uint32_t wd  = (uint32_t)(tid >> 4) * ASTR + (uint32_t)(tid & 15) * 16;
    const uint32_t ad0 = wd;
    const uint32_t ad1 = (uint32_t)((tid + 512) >> 4) * ASTR
                       + (uint32_t)((tid + 512) & 15) * 16;

    for (int t = 0; t < Tlen; ++t) {
        const int p = t & 1;
        for (int l = 0; l < Lnum; ++l) {
            // A tile sources: chunks 0-7 = input, 8-15 = h_{t-1}[l]
            const char *blHi, *blLo;
            if (l == 0) {
                blHi = (const char*)(g_xb_hi + (size_t)t * 8 * 8192);
                blLo = (const char*)(g_xb_lo + (size_t)t * 8 * 8192);
            } else {
                size_t o = (size_t)((p ^ 1) * 4 + (l - 1)) * 8 * 8192;
                blHi = (const char*)g_hb_hi + o * 2;   // bf16 -> bytes
                blLo = (const char*)g_hb_lo + o * 2;
            }
            size_t oh = (size_t)(p * 4 + l) * 8 * 8192;
            const char* bhHi = (const char*)g_hb_hi + oh * 2;
            const char* bhLo = (const char*)g_hb_lo + oh * 2;
            const char* wBaseHi = (const char*)(g_Whi
                + ((((size_t)l * 128 + bx) * 16)) * 4096);
            const char* wBaseLo = (const char*)(g_Wlo
                + ((((size_t)l * 128 + bx) * 16)) * 4096);

            float acc[4] = {0.f, 0.f, 0.f, 0.f};

            // issue chunk ck into buffer buf
            #define ISSUE(ck, buf) do {                                       \
                const char* ah_ = ((ck) < 8) ? blHi + (size_t)(ck) * 16384    \
                                             : bhHi + (size_t)((ck) - 8) * 16384; \
                const char* al_ = ((ck) < 8) ? blLo + (size_t)(ck) * 16384    \
                                             : bhLo + (size_t)((ck) - 8) * 16384; \
                const char* wh_ = wBaseHi + (size_t)(ck) * 8192;              \
                const char* wl_ = wBaseLo + (size_t)(ck) * 8192;              \
                uint32_t aB = sbase + OFF_A + (uint32_t)(buf) * 34816u;       \
                uint32_t wB = sbase + OFF_W + (uint32_t)(buf) * 17408u;       \
                CPA16(wB + wd, wh_ + (size_t)tid * 16);                       \
                CPA16(wB + 8704u + wd, wl_ + (size_t)tid * 16);               \
                CPA16(aB + ad0, ah_ + (size_t)tid * 16);                      \
                CPA16(aB + ad1, ah_ + (size_t)(tid + 512) * 16);              \
                CPA16(aB + 17408u + ad0, al_ + (size_t)tid * 16);             \
                CPA16(aB + 17408u + ad1, al_ + (size_t)(tid + 512) * 16);     \
            } while (0)

            ISSUE(0, 0);
            CPA_COMMIT();

            for (int ck = 0; ck < NCHUNK; ++ck) {
                const int buf = ck & 1;
                __syncthreads();                    // buf^1 free of readers
                if (ck + 1 < NCHUNK) {
                    ISSUE(ck + 1, buf ^ 1);
                    CPA_COMMIT();
                    CPA_WAIT(1);                    // chunk ck landed
                } else {
                    CPA_WAIT(0);
                }
                __syncthreads();

                const uint32_t aH = sbase + OFF_A + (uint32_t)buf * 34816u;
                const uint32_t aL = aH + 17408u;
                const uint32_t wH = sbase + OFF_W + (uint32_t)buf * 17408u;
                const uint32_t wL = wH + 8704u;
                #pragma unroll
                for (int k = 0; k < 8; ++k) {
                    const uint32_t kb = (uint32_t)k * 32;
                    uint32_t ah[4], al[4], bh[2], bl[2];
                    LDSM4(ah, aH + a_off + kb);
                    LDSM4(al, aL + a_off + kb);
                    LDSM2(bh, wH + b_off + kb);
                    LDSM2(bl, wL + b_off + kb);
                    MMA(acc, ah, bh[0], bh[1]);
                    MMA(acc, al, bh[0], bh[1]);
                    MMA(acc, ah, bl[0], bl[1]);
                }
            }
            #undef ISSUE

            // epilogue: stage gates in smem (reuse A region), pointwise
            float* Gs = (float*)(sm + OFF_A);       // [64][33]
            {
                int r  = warpM + (lane >> 2);
                int c0 = warpN + (lane & 3) * 2;
                Gs[r * 33 + c0]           = acc[0];
                Gs[r * 33 + c0 + 1]       = acc[1];
                Gs[(r + 8) * 33 + c0]     = acc[2];
                Gs[(r + 8) * 33 + c0 + 1] = acc[3];
            }
            __syncthreads();

            {
                const float* bias = (const float*)(sm + OFF_BIAS) + l * 32;
                int b  = tid >> 3, hl = tid & 7;
                float gi = Gs[b * 33 + hl]      + bias[hl];
                float gf = Gs[b * 33 + 8 + hl]  + bias[8 + hl];
                float gg = Gs[b * 33 + 16 + hl] + bias[16 + hl];
                float go = Gs[b * 33 + 24 + hl] + bias[24 + hl];
                float ig = sigf(gi), fg = sigf(gf), og = sigf(go);
                float gt = tanhfast(gg);
                float* cp_ = csm + (l * 64 + b) * 8 + hl;
                float cn = fg * (*cp_) + ig * gt;
                *cp_ = cn;
                float hn = og * tanhfast(cn);
                __nv_bfloat16 hh = __float2bfloat16(hn);
                __nv_bfloat16 hlw = __float2bfloat16(hn - __bfloat162float(hh));
                int H = n0 + hl;
                size_t off = ((((size_t)(p ^ 1) * 4 + l) * 8 + (H >> 7)) * 64 + b)
                           * 128 + (H & 127);
                g_hb_hi[off] = hh;
                g_hb_lo[off] = hlw;
                if (t == Tlen - 1 && l == Lnum - 1)
                    g_hfin[(size_t)b * Hdim + H] = hn;
            }

            grid_sync();   // publish h tiles; guards smem/Gs reuse
        }
    }
}

__global__ void fc_kernel(const float* __restrict__ Wfc,
                          const float* __restrict__ bfc,
                          float* __restrict__ out)
{
    const float* h = g_hfin;
    int warp = (blockIdx.x * blockDim.x + threadIdx.x) >> 5;
    int lane = threadIdx.x & 31;
    int b = warp >> 9;
    int o = warp & (Odim - 1);
    const float4* hv = (const float4*)(h   + (size_t)b * Hdim);
    const float4* wv = (const float4*)(Wfc + (size_t)o * Hdim);
    float s = 0.f;
    #pragma unroll
    for (int it = 0; it < 8; ++it) {
        float4 a = hv[it * 32 + lane];
        float4 w = wv[it * 32 + lane];
        s += a.x * w.x + a.y * w.y + a.z * w.z + a.w * w.w;
    }
    #pragma unroll
    for (int off = 16; off; off >>= 1)
        s += __shfl_xor_sync(0xffffffffu, s, off);
    if (lane == 0)
        out[(size_t)b * Odim + o] = s + bfc[o];
}

extern "C" void kernel_launch(void* const* d_in, const int* in_sizes, int n_in,
                              void* d_out, int out_size)
{
    const float* x   = (const float*)d_in[0];
    const float* Wih = (const float*)d_in[1];
    const float* Whh = (const float*)d_in[2];
    const float* bih = (const float*)d_in[3];
    const float* bhh = (const float*)d_in[4];
    const float* Wfc = (const float*)d_in[5];
    const float* bfc = (const float*)d_in[6];
    float* out = (float*)d_out;

    cudaFuncSetAttribute(lstm_persistent,
                         cudaFuncAttributeMaxDynamicSharedMemorySize, SMEM_DYN);

    zero_hb<<<256, 1024>>>();
    prep_x<<<16384, 1024>>>(x);
    prep_weights<<<32768, 1024>>>(Wih, Whh);
    lstm_persistent<<<NBLK, NTHR, SMEM_DYN>>>(bih, bhh);
    fc_kernel<<<(Bsz * Odim) / 8, 256>>>(Wfc, bfc, out);
}

// round 9
// speedup vs baseline: 2.0249x; 1.0226x over previous
#include <cuda_runtime.h>
#include <cuda_bf16.h>
#include <stdint.h>
#include <math.h>

#define Bsz  64
#define Tlen 256
#define Hdim 1024
#define Lnum 4
#define Odim 512
#define NBLK 128
#define NTHR 512
#define NCHUNK 16
#define ASTR 272              // smem row pitch (256B row + 16B pad)
#define ASLOT 34816u          // A hi+lo per chunk
#define WSLOT 17408u          // W hi+lo per chunk

// ---- persistent device state ----
__device__ __nv_bfloat16 g_Whi[(size_t)Lnum * 128 * 16 * 32 * 128];  // 64 MB
__device__ __nv_bfloat16 g_Wlo[(size_t)Lnum * 128 * 16 * 32 * 128];  // 64 MB
__device__ __nv_bfloat16 g_xb_hi[(size_t)Tlen * 8 * 64 * 128];       // 32 MB
__device__ __nv_bfloat16 g_xb_lo[(size_t)Tlen * 8 * 64 * 128];       // 32 MB
__device__ __nv_bfloat16 g_hb_hi[2 * Lnum * 8 * 64 * 128];           // 1 MB
__device__ __nv_bfloat16 g_hb_lo[2 * Lnum * 8 * 64 * 128];           // 1 MB
__device__ float g_hfin[Bsz * Hdim];

__device__ volatile unsigned g_gen = 0;
__device__ unsigned g_count = 0;

__device__ __forceinline__ void grid_sync() {
    __syncthreads();
    if (threadIdx.x == 0) {
        __threadfence();
        unsigned my = g_gen;
        if (atomicAdd(&g_count, 1u) == NBLK - 1) {
            g_count = 0; __threadfence(); g_gen = my + 1;
        } else {
            while (g_gen == my) { __nanosleep(20); }
        }
        __threadfence();
    }
    __syncthreads();
}

__device__ __forceinline__ uint32_t smem_u32(const void* p) {
    uint32_t a;
    asm("{ .reg .u64 t; cvta.to.shared.u64 t, %1; cvt.u32.u64 %0, t; }"
        : "=r"(a) : "l"(p));
    return a;
}
__device__ __forceinline__ float ex2f(float x) {
    float r; asm("ex2.approx.f32 %0, %1;" : "=f"(r) : "f"(x)); return r;
}
__device__ __forceinline__ float rcpf(float x) {
    float r; asm("rcp.approx.f32 %0, %1;" : "=f"(r) : "f"(x)); return r;
}
__device__ __forceinline__ float sigf(float x) {
    return rcpf(1.0f + ex2f(-1.4426950408889634f * x));
}
__device__ __forceinline__ float tanhfast(float x) {
    float e = ex2f(2.8853900817779268f * x);
    return 1.0f - 2.0f * rcpf(e + 1.0f);
}

#define LDSM4(r, a)                                                           \
    asm volatile("ldmatrix.sync.aligned.m8n8.x4.shared.b16 {%0,%1,%2,%3}, [%4];" \
        : "=r"((r)[0]), "=r"((r)[1]), "=r"((r)[2]), "=r"((r)[3]) : "r"(a))
#define LDSM2(r, a)                                                           \
    asm volatile("ldmatrix.sync.aligned.m8n8.x2.shared.b16 {%0,%1}, [%2];"    \
        : "=r"((r)[0]), "=r"((r)[1]) : "r"(a))

#define MMA(d, a, b0, b1)                                                     \
    asm volatile("mma.sync.aligned.m16n8k16.row.col.f32.bf16.bf16.f32 "       \
        "{%0,%1,%2,%3},{%4,%5,%6,%7},{%8,%9},{%0,%1,%2,%3};"                  \
        : "+f"((d)[0]), "+f"((d)[1]), "+f"((d)[2]), "+f"((d)[3])              \
        : "r"((a)[0]), "r"((a)[1]), "r"((a)[2]), "r"((a)[3]),                 \
          "r"(b0), "r"(b1))

#define CPA16(dst, src) \
    asm volatile("cp.async.ca.shared.global [%0], [%1], 16;" :: "r"(dst), "l"(src))
#define CPA_COMMIT() asm volatile("cp.async.commit_group;" ::: "memory")
#define CPA_WAIT(n)  asm volatile("cp.async.wait_group %0;" :: "n"(n) : "memory")

// smem layout: bias | c | 4 A slots | 4 W slots
#define OFF_BIAS 0
#define OFF_C    512
#define OFF_A    8704
#define OFF_W    (8704 + 4 * 34816)      // 147968
#define SMEM_DYN (OFF_W + 4 * 17408)     // 217600

__global__ void zero_hb() {
    int i = blockIdx.x * 1024 + threadIdx.x;
    g_hb_hi[i] = __float2bfloat16(0.f);
    g_hb_lo[i] = __float2bfloat16(0.f);
}

__global__ void prep_x(const float* __restrict__ x) {
    size_t idx = (size_t)blockIdx.x * 1024 + threadIdx.x;   // 2^24
    int c  = (int)(idx & 127);
    int b  = (int)((idx >> 7) & 63);
    int ck = (int)((idx >> 13) & 7);
    int t  = (int)(idx >> 16);
    float v = x[((size_t)b * Tlen + t) * 1024 + ck * 128 + c];
    __nv_bfloat16 h = __float2bfloat16(v);
    size_t dst = (((size_t)(t * 8 + ck)) * 64 + b) * 128 + c;
    g_xb_hi[dst] = h;
    g_xb_lo[dst] = __float2bfloat16(v - __bfloat162float(h));
}

__global__ void prep_weights(const float* __restrict__ Wih,
                             const float* __restrict__ Whh) {
    size_t idx = (size_t)blockIdx.x * 1024 + threadIdx.x;   // 2^25
    int c  = (int)(idx & 127);
    int n  = (int)((idx >> 7) & 31);
    int ck = (int)((idx >> 12) & 15);
    int nb = (int)((idx >> 16) & 127);
    int l  = (int)(idx >> 23);
    int gate = n >> 3, hid = nb * 8 + (n & 7);
    int kk = ck * 128 + c;
    size_t grow = (size_t)l * 4096 * 1024 + (size_t)(gate * 1024 + hid) * 1024;
    float v = (kk < 1024) ? Wih[grow + kk] : Whh[grow + kk - 1024];
    __nv_bfloat16 h = __float2bfloat16(v);
    size_t e = ((((size_t)l * 128 + nb) * 16) + ck) * 4096 + (size_t)n * 128 + c;
    g_Whi[e] = h;
    g_Wlo[e] = __float2bfloat16(v - __bfloat162float(h));
}

__global__ __launch_bounds__(NTHR, 1) void lstm_persistent(
    const float* __restrict__ bih, const float* __restrict__ bhh)
{
    extern __shared__ char sm[];
    const uint32_t sbase = smem_u32(sm);

    const int tid  = threadIdx.x;
    const int wid  = tid >> 5;
    const int lane = tid & 31;
    const int bx   = blockIdx.x;
    const int n0   = bx * 8;
    const int warpM = (wid & 3) * 16;
    const int warpN = (wid >> 2) * 8;

    if (tid < Lnum * 32) {
        int li = tid >> 5, col = tid & 31;
        int gate = col >> 3, hid = n0 + (col & 7);
        int row = li * 4096 + gate * 1024 + hid;
        ((float*)(sm + OFF_BIAS))[li * 32 + col] = bih[row] + bhh[row];
    }
    float* csm = (float*)(sm + OFF_C);
    #pragma unroll
    for (int i = 0; i < 4; ++i)
        csm[i * NTHR + tid] = 0.f;
    __syncthreads();

    const uint32_t a_off = (uint32_t)(warpM + (lane & 15)) * ASTR
                         + ((uint32_t)(lane >> 4) << 4);
    const uint32_t b_off = (uint32_t)(warpN + (lane & 7)) * ASTR
                         + (((uint32_t)(lane >> 3) & 1u) << 4);
    const uint32_t wd  = (uint32_t)(tid >> 4) * ASTR + (uint32_t)(tid & 15) * 16;
    const uint32_t ad0 = wd;
    const uint32_t ad1 = (uint32_t)((tid + 512) >> 4) * ASTR
                       + (uint32_t)((tid + 512) & 15) * 16;

    for (int t = 0; t < Tlen; ++t) {
        const int p = t & 1;
        for (int l = 0; l < Lnum; ++l) {
            const char *blHi, *blLo;
            if (l == 0) {
                blHi = (const char*)(g_xb_hi + (size_t)t * 8 * 8192);
                blLo = (const char*)(g_xb_lo + (size_t)t * 8 * 8192);
            } else {
                size_t o = (size_t)((p ^ 1) * 4 + (l - 1)) * 8 * 8192;
                blHi = (const char*)g_hb_hi + o * 2;
                blLo = (const char*)g_hb_lo + o * 2;
            }
            size_t oh = (size_t)(p * 4 + l) * 8 * 8192;
            const char* bhHi = (const char*)g_hb_hi + oh * 2;
            const char* bhLo = (const char*)g_hb_lo + oh * 2;
            const char* wBaseHi = (const char*)(g_Whi
                + ((((size_t)l * 128 + bx) * 16)) * 4096);
            const char* wBaseLo = (const char*)(g_Wlo
                + ((((size_t)l * 128 + bx) * 16)) * 4096);

            // three independent accumulator chains (one per precision pass)
            float acc0[4] = {0,0,0,0}, acc1[4] = {0,0,0,0}, acc2[4] = {0,0,0,0};

            #define ISSUE(ck, slot) do {                                      \
                const char* ah_ = ((ck) < 8) ? blHi + (size_t)(ck) * 16384    \
                                             : bhHi + (size_t)((ck) - 8) * 16384; \
                const char* al_ = ((ck) < 8) ? blLo + (size_t)(ck) * 16384    \
                                             : bhLo + (size_t)((ck) - 8) * 16384; \
                const char* wh_ = wBaseHi + (size_t)(ck) * 8192;              \
                const char* wl_ = wBaseLo + (size_t)(ck) * 8192;              \
                uint32_t aB = sbase + OFF_A + (uint32_t)(slot) * ASLOT;       \
                uint32_t wB = sbase + OFF_W + (uint32_t)(slot) * WSLOT;       \
                CPA16(wB + wd, wh_ + (size_t)tid * 16);                       \
                CPA16(wB + 8704u + wd, wl_ + (size_t)tid * 16);               \
                CPA16(aB + ad0, ah_ + (size_t)tid * 16);                      \
                CPA16(aB + ad1, ah_ + (size_t)(tid + 512) * 16);              \
                CPA16(aB + 17408u + ad0, al_ + (size_t)tid * 16);             \
                CPA16(aB + 17408u + ad1, al_ + (size_t)(tid + 512) * 16);     \
            } while (0)

            // prologue: fill 3 of 4 pipeline slots
            ISSUE(0, 0); CPA_COMMIT();
            ISSUE(1, 1); CPA_COMMIT();
            ISSUE(2, 2); CPA_COMMIT();

            for (int ck = 0; ck < NCHUNK; ++ck) {
                const int slot = ck & 3;
                // wait until chunk ck landed (own thread's groups)
                if (ck < NCHUNK - 2)      CPA_WAIT(2);
                else if (ck == NCHUNK - 2) CPA_WAIT(1);
                else                       CPA_WAIT(0);
                __syncthreads();   // data visible to all; prev readers done
                if (ck + 3 < NCHUNK) {
                    ISSUE(ck + 3, (ck + 3) & 3);
                    CPA_COMMIT();
                }

                const uint32_t aH = sbase + OFF_A + (uint32_t)slot * ASLOT;
                const uint32_t aL = aH + 17408u;
                const uint32_t wH = sbase + OFF_W + (uint32_t)slot * WSLOT;
                const uint32_t wL = wH + 8704u;
                #pragma unroll
                for (int k = 0; k < 8; ++k) {
                    const uint32_t kb = (uint32_t)k * 32;
                    uint32_t ah[4], al[4], bh[2], bl[2];
                    LDSM4(ah, aH + a_off + kb);
                    LDSM4(al, aL + a_off + kb);
                    LDSM2(bh, wH + b_off + kb);
                    LDSM2(bl, wL + b_off + kb);
                    MMA(acc0, ah, bh[0], bh[1]);
                    MMA(acc1, al, bh[0], bh[1]);
                    MMA(acc2, ah, bl[0], bl[1]);
                }
            }
            #undef ISSUE

            __syncthreads();   // all warps done reading slots before Gs reuse

            float* Gs = (float*)(sm + OFF_A);       // [64][33]
            {
                int r  = warpM + (lane >> 2);
                int c0 = warpN + (lane & 3) * 2;
                Gs[r * 33 + c0]           = acc0[0] + acc1[0] + acc2[0];
                Gs[r * 33 + c0 + 1]       = acc0[1] + acc1[1] + acc2[1];
                Gs[(r + 8) * 33 + c0]     = acc0[2] + acc1[2] + acc2[2];
                Gs[(r + 8) * 33 + c0 + 1] = acc0[3] + acc1[3] + acc2[3];
            }
            __syncthreads();

            {
                const float* bias = (const float*)(sm + OFF_BIAS) + l * 32;
                int b  = tid >> 3, hl = tid & 7;
                float gi = Gs[b * 33 + hl]      + bias[hl];
                float gf = Gs[b * 33 + 8 + hl]  + bias[8 + hl];
                float gg = Gs[b * 33 + 16 + hl] + bias[16 + hl];
                float go = Gs[b * 33 + 24 + hl] + bias[24 + hl];
                float ig = sigf(gi), fg = sigf(gf), og = sigf(go);
                float gt = tanhfast(gg);
                float* cp_ = csm + (l * 64 + b) * 8 + hl;
                float cn = fg * (*cp_) + ig * gt;
                *cp_ = cn;
                float hn = og * tanhfast(cn);
                __nv_bfloat16 hh = __float2bfloat16(hn);
                __nv_bfloat16 hlw = __float2bfloat16(hn - __bfloat162float(hh));
                int H = n0 + hl;
                size_t off = ((((size_t)(p ^ 1) * 4 + l) * 8 + (H >> 7)) * 64 + b)
                           * 128 + (H & 127);
                g_hb_hi[off] = hh;
                g_hb_lo[off] = hlw;
                if (t == Tlen - 1 && l == Lnum - 1)
                    g_hfin[(size_t)b * Hdim + H] = hn;
            }

            grid_sync();
        }
    }
}

__global__ void fc_kernel(const float* __restrict__ Wfc,
                          const float* __restrict__ bfc,
                          float* __restrict__ out)
{
    const float* h = g_hfin;
    int warp = (blockIdx.x * blockDim.x + threadIdx.x) >> 5;
    int lane = threadIdx.x & 31;
    int b = warp >> 9;
    int o = warp & (Odim - 1);
    const float4* hv = (const float4*)(h   + (size_t)b * Hdim);
    const float4* wv = (const float4*)(Wfc + (size_t)o * Hdim);
    float s = 0.f;
    #pragma unroll
    for (int it = 0; it < 8; ++it) {
        float4 a = hv[it * 32 + lane];
        float4 w = wv[it * 32 + lane];
        s += a.x * w.x + a.y * w.y + a.z * w.z + a.w * w.w;
    }
    #pragma unroll
    for (int off = 16; off; off >>= 1)
        s += __shfl_xor_sync(0xffffffffu, s, off);
    if (lane == 0)
        out[(size_t)b * Odim + o] = s + bfc[o];
}

extern "C" void kernel_launch(void* const* d_in, const int* in_sizes, int n_in,
                              void* d_out, int out_size)
{
    const float* x   = (const float*)d_in[0];
    const float* Wih = (const float*)d_in[1];
    const float* Whh = (const float*)d_in[2];
    const float* bih = (const float*)d_in[3];
    const float* bhh = (const float*)d_in[4];
    const float* Wfc = (const float*)d_in[5];
    const float* bfc = (const float*)d_in[6];
    float* out = (float*)d_out;

    cudaFuncSetAttribute(lstm_persistent,
                         cudaFuncAttributeMaxDynamicSharedMemorySize, SMEM_DYN);

    zero_hb<<<256, 1024>>>();
    prep_x<<<16384, 1024>>>(x);
    prep_weights<<<32768, 1024>>>(Wih, Whh);
    lstm_persistent<<<NBLK, NTHR, SMEM_DYN>>>(bih, bhh);
    fc_kernel<<<(Bsz * Odim) / 8, 256>>>(Wfc, bfc, out);
}

// round 10
// speedup vs baseline: 2.3591x; 1.1650x over previous
#include <cuda_runtime.h>
#include <cuda_bf16.h>
#include <stdint.h>
#include <math.h>

#define Bsz  64
#define Tlen 256
#define Hdim 1024
#define Lnum 4
#define Odim 512
#define NBLK 128
#define NTHR 512
#define NCHUNK 16
#define ASTR 272              // smem row pitch (256B row + 16B pad)
#define ASLOT 34816u          // A hi+lo per chunk
#define WSLOT 17408u          // W hi+lo per chunk

// ---- persistent device state ----
__device__ __nv_bfloat16 g_Whi[(size_t)Lnum * 128 * 16 * 32 * 128];  // 64 MB
__device__ __nv_bfloat16 g_Wlo[(size_t)Lnum * 128 * 16 * 32 * 128];  // 64 MB
__device__ __nv_bfloat16 g_xb_hi[(size_t)Tlen * 8 * 64 * 128];       // 32 MB
__device__ __nv_bfloat16 g_xb_lo[(size_t)Tlen * 8 * 64 * 128];       // 32 MB
__device__ __nv_bfloat16 g_hb_hi[2 * Lnum * 8 * 64 * 128];           // 1 MB
__device__ __nv_bfloat16 g_hb_lo[2 * Lnum * 8 * 64 * 128];           // 1 MB
__device__ float g_hfin[Bsz * Hdim];

__device__ volatile unsigned g_gen = 0;
__device__ unsigned g_count = 0;

__device__ __forceinline__ void grid_sync() {
    __syncthreads();
    if (threadIdx.x == 0) {
        __threadfence();
        unsigned my = g_gen;
        if (atomicAdd(&g_count, 1u) == NBLK - 1) {
            g_count = 0; __threadfence(); g_gen = my + 1;
        } else {
            while (g_gen == my) { __nanosleep(20); }
        }
        __threadfence();
    }
    __syncthreads();
}

__device__ __forceinline__ uint32_t smem_u32(const void* p) {
    uint32_t a;
    asm("{ .reg .u64 t; cvta.to.shared.u64 t, %1; cvt.u32.u64 %0, t; }"
        : "=r"(a) : "l"(p));
    return a;
}
__device__ __forceinline__ float ex2f(float x) {
    float r; asm("ex2.approx.f32 %0, %1;" : "=f"(r) : "f"(x)); return r;
}
__device__ __forceinline__ float rcpf(float x) {
    float r; asm("rcp.approx.f32 %0, %1;" : "=f"(r) : "f"(x)); return r;
}
__device__ __forceinline__ float sigf(float x) {
    return rcpf(1.0f + ex2f(-1.4426950408889634f * x));
}
__device__ __forceinline__ float tanhfast(float x) {
    float e = ex2f(2.8853900817779268f * x);
    return 1.0f - 2.0f * rcpf(e + 1.0f);
}

#define LDSM4(r, a)                                                           \
    asm volatile("ldmatrix.sync.aligned.m8n8.x4.shared.b16 {%0,%1,%2,%3}, [%4];" \
        : "=r"((r)[0]), "=r"((r)[1]), "=r"((r)[2]), "=r"((r)[3]) : "r"(a))

#define MMA(d, a0, a1, a2, a3, b0, b1)                                        \
    asm volatile("mma.sync.aligned.m16n8k16.row.col.f32.bf16.bf16.f32 "       \
        "{%0,%1,%2,%3},{%4,%5,%6,%7},{%8,%9},{%0,%1,%2,%3};"                  \
        : "+f"((d)[0]), "+f"((d)[1]), "+f"((d)[2]), "+f"((d)[3])              \
        : "r"(a0), "r"(a1), "r"(a2), "r"(a3), "r"(b0), "r"(b1))

#define CPA16(dst, src) \
    asm volatile("cp.async.ca.shared.global [%0], [%1], 16;" :: "r"(dst), "l"(src))
#define CPA_COMMIT() asm volatile("cp.async.commit_group;" ::: "memory")
#define CPA_WAIT(n)  asm volatile("cp.async.wait_group %0;" :: "n"(n) : "memory")

// smem layout: bias | c | 4 A slots | 4 W slots
#define OFF_BIAS 0
#define OFF_C    512
#define OFF_A    8704
#define OFF_W    (8704 + 4 * 34816)      // 147968
#define SMEM_DYN (OFF_W + 4 * 17408)     // 217600

__global__ void zero_hb() {
    int i = blockIdx.x * 1024 + threadIdx.x;
    g_hb_hi[i] = __float2bfloat16(0.f);
    g_hb_lo[i] = __float2bfloat16(0.f);
}

__global__ void prep_x(const float* __restrict__ x) {
    size_t idx = (size_t)blockIdx.x * 1024 + threadIdx.x;   // 2^24
    int c  = (int)(idx & 127);
    int b  = (int)((idx >> 7) & 63);
    int ck = (int)((idx >> 13) & 7);
    int t  = (int)(idx >> 16);
    float v = x[((size_t)b * Tlen + t) * 1024 + ck * 128 + c];
    __nv_bfloat16 h = __float2bfloat16(v);
    size_t dst = (((size_t)(t * 8 + ck)) * 64 + b) * 128 + c;
    g_xb_hi[dst] = h;
    g_xb_lo[dst] = __float2bfloat16(v - __bfloat162float(h));
}

__global__ void prep_weights(const float* __restrict__ Wih,
                             const float* __restrict__ Whh) {
    size_t idx = (size_t)blockIdx.x * 1024 + threadIdx.x;   // 2^25
    int c  = (int)(idx & 127);
    int n  = (int)((idx >> 7) & 31);
    int ck = (int)((idx >> 12) & 15);
    int nb = (int)((idx >> 16) & 127);
    int l  = (int)(idx >> 23);
    int gate = n >> 3, hid = nb * 8 + (n & 7);
    int kk = ck * 128 + c;
    size_t grow = (size_t)l * 4096 * 1024 + (size_t)(gate * 1024 + hid) * 1024;
    float v = (kk < 1024) ? Wih[grow + kk] : Whh[grow + kk - 1024];
    __nv_bfloat16 h = __float2bfloat16(v);
    size_t e = ((((size_t)l * 128 + nb) * 16) + ck) * 4096 + (size_t)n * 128 + c;
    g_Whi[e] = h;
    g_Wlo[e] = __float2bfloat16(v - __bfloat162float(h));
}

__global__ __launch_bounds__(NTHR, 1) void lstm_persistent(
    const float* __restrict__ bih, const float* __restrict__ bhh)
{
    extern __shared__ char sm[];
    const uint32_t sbase = smem_u32(sm);

    const int tid  = threadIdx.x;
    const int wid  = tid >> 5;
    const int lane = tid & 31;
    const int bx   = blockIdx.x;
    const int n0   = bx * 8;
    // warp tiling: m32 x n16, 4-way K-split
    const int mt = wid & 1;           // m-tile (rows mt*32 .. +31)
    const int nt = (wid >> 1) & 1;    // n-tile (cols nt*16 .. +15)
    const int kg = wid >> 2;          // k-group: k-steps {2kg, 2kg+1}

    if (tid < Lnum * 32) {
        int li = tid >> 5, col = tid & 31;
        int gate = col >> 3, hid = n0 + (col & 7);
        int row = li * 4096 + gate * 1024 + hid;
        ((float*)(sm + OFF_BIAS))[li * 32 + col] = bih[row] + bhh[row];
    }
    float* csm = (float*)(sm + OFF_C);
    #pragma unroll
    for (int i = 0; i < 4; ++i)
        csm[i * NTHR + tid] = 0.f;
    __syncthreads();

    // ldmatrix per-lane offsets
    const uint32_t a_off0 = (uint32_t)(mt * 32 + (lane & 15)) * ASTR
                          + ((uint32_t)(lane >> 4) << 4);          // rows +0..15
    const uint32_t a_off1 = a_off0 + 16u * ASTR;                   // rows +16..31
    const uint32_t b_off  = (uint32_t)(nt * 16 + (lane & 7) + ((lane >> 4) << 3)) * ASTR
                          + (((uint32_t)(lane >> 3) & 1u) << 4);
    // cp.async per-thread dest offsets
    const uint32_t wd  = (uint32_t)(tid >> 4) * ASTR + (uint32_t)(tid & 15) * 16;
    const uint32_t ad0 = wd;
    const uint32_t ad1 = (uint32_t)((tid + 512) >> 4) * ASTR
                       + (uint32_t)((tid + 512) & 15) * 16;
    const uint32_t kb0 = (uint32_t)(kg * 2) * 32;   // first k-step byte offset

    for (int t = 0; t < Tlen; ++t) {
        const int p = t & 1;
        for (int l = 0; l < Lnum; ++l) {
            const char *blHi, *blLo;
            if (l == 0) {
                blHi = (const char*)(g_xb_hi + (size_t)t * 8 * 8192);
                blLo = (const char*)(g_xb_lo + (size_t)t * 8 * 8192);
            } else {
                size_t o = (size_t)((p ^ 1) * 4 + (l - 1)) * 8 * 8192;
                blHi = (const char*)g_hb_hi + o * 2;
                blLo = (const char*)g_hb_lo + o * 2;
            }
            size_t oh = (size_t)(p * 4 + l) * 8 * 8192;
            const char* bhHi = (const char*)g_hb_hi + oh * 2;
            const char* bhLo = (const char*)g_hb_lo + oh * 2;
            const char* wBaseHi = (const char*)(g_Whi
                + ((((size_t)l * 128 + bx) * 16)) * 4096);
            const char* wBaseLo = (const char*)(g_Wlo
                + ((((size_t)l * 128 + bx) * 16)) * 4096);

            // 3 chains x 4 sub-tiles (msub*2+nsub), 4 regs each = 48 acc regs
            float c0[4][4] = {}, c1[4][4] = {}, c2[4][4] = {};

            #define ISSUE(ck, slot) do {                                      \
                const char* ah_ = ((ck) < 8) ? blHi + (size_t)(ck) * 16384    \
                                             : bhHi + (size_t)((ck) - 8) * 16384; \
                const char* al_ = ((ck) < 8) ? blLo + (size_t)(ck) * 16384    \
                                             : bhLo + (size_t)((ck) - 8) * 16384; \
                const char* wh_ = wBaseHi + (size_t)(ck) * 8192;              \
                const char* wl_ = wBaseLo + (size_t)(ck) * 8192;              \
                uint32_t aB = sbase + OFF_A + (uint32_t)(slot) * ASLOT;       \
                uint32_t wB = sbase + OFF_W + (uint32_t)(slot) * WSLOT;       \
                CPA16(wB + wd, wh_ + (size_t)tid * 16);                       \
                CPA16(wB + 8704u + wd, wl_ + (size_t)tid * 16);               \
                CPA16(aB + ad0, ah_ + (size_t)tid * 16);                      \
                CPA16(aB + ad1, ah_ + (size_t)(tid + 512) * 16);              \
                CPA16(aB + 17408u + ad0, al_ + (size_t)tid * 16);             \
                CPA16(aB + 17408u + ad1, al_ + (size_t)(tid + 512) * 16);     \
            } while (0)

            ISSUE(0, 0); CPA_COMMIT();
            ISSUE(1, 1); CPA_COMMIT();
            ISSUE(2, 2); CPA_COMMIT();

            for (int ck = 0; ck < NCHUNK; ++ck) {
                const int slot = ck & 3;
                if (ck < NCHUNK - 2)       CPA_WAIT(2);
                else if (ck == NCHUNK - 2) CPA_WAIT(1);
                else                       CPA_WAIT(0);
                __syncthreads();
                if (ck + 3 < NCHUNK) {
                    ISSUE(ck + 3, (ck + 3) & 3);
                    CPA_COMMIT();
                }

                const uint32_t aH = sbase + OFF_A + (uint32_t)slot * ASLOT;
                const uint32_t aL = aH + 17408u;
                const uint32_t wH = sbase + OFF_W + (uint32_t)slot * WSLOT;
                const uint32_t wL = wH + 8704u;
                #pragma unroll
                for (int kk = 0; kk < 2; ++kk) {
                    const uint32_t kb = kb0 + (uint32_t)kk * 32;
                    uint32_t ah0[4], ah1[4], al0[4], al1[4], bh[4], bl[4];
                    LDSM4(ah0, aH + a_off0 + kb);
                    LDSM4(ah1, aH + a_off1 + kb);
                    LDSM4(al0, aL + a_off0 + kb);
                    LDSM4(al1, aL + a_off1 + kb);
                    LDSM4(bh,  wH + b_off + kb);
                    LDSM4(bl,  wL + b_off + kb);
                    // chain 0: Ahi * Whi
                    MMA(c0[0], ah0[0],ah0[1],ah0[2],ah0[3], bh[0], bh[1]);
                    MMA(c0[1], ah0[0],ah0[1],ah0[2],ah0[3], bh[2], bh[3]);
                    MMA(c0[2], ah1[0],ah1[1],ah1[2],ah1[3], bh[0], bh[1]);
                    MMA(c0[3], ah1[0],ah1[1],ah1[2],ah1[3], bh[2], bh[3]);
                    // chain 1: Alo * Whi
                    MMA(c1[0], al0[0],al0[1],al0[2],al0[3], bh[0], bh[1]);
                    MMA(c1[1], al0[0],al0[1],al0[2],al0[3], bh[2], bh[3]);
                    MMA(c1[2], al1[0],al1[1],al1[2],al1[3], bh[0], bh[1]);
                    MMA(c1[3], al1[0],al1[1],al1[2],al1[3], bh[2], bh[3]);
                    // chain 2: Ahi * Wlo
                    MMA(c2[0], ah0[0],ah0[1],ah0[2],ah0[3], bl[0], bl[1]);
                    MMA(c2[1], ah0[0],ah0[1],ah0[2],ah0[3], bl[2], bl[3]);
                    MMA(c2[2], ah1[0],ah1[1],ah1[2],ah1[3], bl[0], bl[1]);
                    MMA(c2[3], ah1[0],ah1[1],ah1[2],ah1[3], bl[2], bl[3]);
                }
            }
            #undef ISSUE

            __syncthreads();   // slots free before Gs reuse

            // partial gates per k-group: Gs[4][64][33]
            float* Gs = (float*)(sm + OFF_A);
            #pragma unroll
            for (int j = 0; j < 4; ++j) {
                int msub = j >> 1, nsub = j & 1;
                int R = mt * 32 + msub * 16 + (lane >> 2);
                int C = nt * 16 + nsub * 8 + (lane & 3) * 2;
                int base = (kg * 64 + R) * 33 + C;
                Gs[base]     = c0[j][0] + c1[j][0] + c2[j][0];
                Gs[base + 1] = c0[j][1] + c1[j][1] + c2[j][1];
                Gs[base + 8 * 33]     = c0[j][2] + c1[j][2] + c2[j][2];
                Gs[base + 8 * 33 + 1] = c0[j][3] + c1[j][3] + c2[j][3];
            }
            __syncthreads();

            {
                const float* bias = (const float*)(sm + OFF_BIAS) + l * 32;
                int b  = tid >> 3, hl = tid & 7;
                float g[4];
                #pragma unroll
                for (int gate = 0; gate < 4; ++gate) {
                    int c = gate * 8 + hl;
                    g[gate] = Gs[(0 * 64 + b) * 33 + c]
                            + Gs[(1 * 64 + b) * 33 + c]
                            + Gs[(2 * 64 + b) * 33 + c]
                            + Gs[(3 * 64 + b) * 33 + c]
                            + bias[c];
                }
                float ig = sigf(g[0]), fg = sigf(g[1]), og = sigf(g[3]);
                float gt = tanhfast(g[2]);
                float* cp_ = csm + (l * 64 + b) * 8 + hl;
                float cn = fg * (*cp_) + ig * gt;
                *cp_ = cn;
                float hn = og * tanhfast(cn);
                __nv_bfloat16 hh = __float2bfloat16(hn);
                __nv_bfloat16 hlw = __float2bfloat16(hn - __bfloat162float(hh));
                int H = n0 + hl;
                size_t off = ((((size_t)(p ^ 1) * 4 + l) * 8 + (H >> 7)) * 64 + b)
                           * 128 + (H & 127);
                g_hb_hi[off] = hh;
                g_hb_lo[off] = hlw;
                if (t == Tlen - 1 && l == Lnum - 1)
                    g_hfin[(size_t)b * Hdim + H] = hn;
            }

            grid_sync();
        }
    }
}

__global__ void fc_kernel(const float* __restrict__ Wfc,
                          const float* __restrict__ bfc,
                          float* __restrict__ out)
{
    const float* h = g_hfin;
    int warp = (blockIdx.x * blockDim.x + threadIdx.x) >> 5;
    int lane = threadIdx.x & 31;
    int b = warp >> 9;
    int o = warp & (Odim - 1);
    const float4* hv = (const float4*)(h   + (size_t)b * Hdim);
    const float4* wv = (const float4*)(Wfc + (size_t)o * Hdim);
    float s = 0.f;
    #pragma unroll
    for (int it = 0; it < 8; ++it) {
        float4 a = hv[it * 32 + lane];
        float4 w = wv[it * 32 + lane];
        s += a.x * w.x + a.y * w.y + a.z * w.z + a.w * w.w;
    }
    #pragma unroll
    for (int off = 16; off; off >>= 1)
        s += __shfl_xor_sync(0xffffffffu, s, off);
    if (lane == 0)
        out[(size_t)b * Odim + o] = s + bfc[o];
}

extern "C" void kernel_launch(void* const* d_in, const int* in_sizes, int n_in,
                              void* d_out, int out_size)
{
    const float* x   = (const float*)d_in[0];
    const float* Wih = (const float*)d_in[1];
    const float* Whh = (const float*)d_in[2];
    const float* bih = (const float*)d_in[3];
    const float* bhh = (const float*)d_in[4];
    const float* Wfc = (const float*)d_in[5];
    const float* bfc = (const float*)d_in[6];
    float* out = (float*)d_out;

    cudaFuncSetAttribute(lstm_persistent,
                         cudaFuncAttributeMaxDynamicSharedMemorySize, SMEM_DYN);

    zero_hb<<<256, 1024>>>();
    prep_x<<<16384, 1024>>>(x);
    prep_weights<<<32768, 1024>>>(Wih, Whh);
    lstm_persistent<<<NBLK, NTHR, SMEM_DYN>>>(bih, bhh);
    fc_kernel<<<(Bsz * Odim) / 8, 256>>>(Wfc, bfc, out);
}

// round 11
// speedup vs baseline: 3.5873x; 1.5206x over previous
#include <cuda_runtime.h>
#include <cuda_bf16.h>
#include <stdint.h>
#include <math.h>

#define Bsz  64
#define Tlen 256
#define Hdim 1024
#define Lnum 4
#define Odim 512
#define NBLK 128
#define NTHR 512
#define NCHUNK 16
#define NSTEP (Tlen + Lnum - 1)    // 259 wavefront steps
#define ASTR 272                   // smem row pitch bytes
#define AHALF 17408u               // 64 rows * 272
#define ASLOT 34816u               // A hi+lo
#define WHALF 34816u               // 128 rows * 272
#define WSLOT 69632u               // W hi+lo

// ---- persistent device state ----
// weights: per (l, nb 0..31, ck 0..15) a 128x128 bf16 tile (rows n = gate*32+hid)
__device__ __nv_bfloat16 g_Whi[(size_t)Lnum * 32 * 16 * 128 * 128];  // 64 MB
__device__ __nv_bfloat16 g_Wlo[(size_t)Lnum * 32 * 16 * 128 * 128];  // 64 MB
__device__ __nv_bfloat16 g_xb_hi[(size_t)Tlen * 8 * 64 * 128];       // 32 MB
__device__ __nv_bfloat16 g_xb_lo[(size_t)Tlen * 8 * 64 * 128];       // 32 MB
// h tiles: [l][parity][ck 8][row b 64][col 128]
__device__ __nv_bfloat16 g_hb_hi[Lnum * 2 * 8 * 64 * 128];           // 1 MB
__device__ __nv_bfloat16 g_hb_lo[Lnum * 2 * 8 * 64 * 128];           // 1 MB
__device__ float g_hfin[Bsz * Hdim];

__device__ volatile unsigned g_gen = 0;
__device__ unsigned g_count = 0;

__device__ __forceinline__ void grid_sync() {
    __syncthreads();
    if (threadIdx.x == 0) {
        __threadfence();
        unsigned my = g_gen;
        if (atomicAdd(&g_count, 1u) == NBLK - 1) {
            g_count = 0; __threadfence(); g_gen = my + 1;
        } else {
            while (g_gen == my) { __nanosleep(20); }
        }
        __threadfence();
    }
    __syncthreads();
}

__device__ __forceinline__ uint32_t smem_u32(const void* p) {
    uint32_t a;
    asm("{ .reg .u64 t; cvta.to.shared.u64 t, %1; cvt.u32.u64 %0, t; }"
        : "=r"(a) : "l"(p));
    return a;
}
__device__ __forceinline__ float ex2f(float x) {
    float r; asm("ex2.approx.f32 %0, %1;" : "=f"(r) : "f"(x)); return r;
}
__device__ __forceinline__ float rcpf(float x) {
    float r; asm("rcp.approx.f32 %0, %1;" : "=f"(r) : "f"(x)); return r;
}
__device__ __forceinline__ float sigf(float x) {
    return rcpf(1.0f + ex2f(-1.4426950408889634f * x));
}
__device__ __forceinline__ float tanhfast(float x) {
    float e = ex2f(2.8853900817779268f * x);
    return 1.0f - 2.0f * rcpf(e + 1.0f);
}

#define LDSM4(r, a)                                                           \
    asm volatile("ldmatrix.sync.aligned.m8n8.x4.shared.b16 {%0,%1,%2,%3}, [%4];" \
        : "=r"((r)[0]), "=r"((r)[1]), "=r"((r)[2]), "=r"((r)[3]) : "r"(a))

#define MMA(d, a, b0, b1)                                                     \
    asm volatile("mma.sync.aligned.m16n8k16.row.col.f32.bf16.bf16.f32 "       \
        "{%0,%1,%2,%3},{%4,%5,%6,%7},{%8,%9},{%0,%1,%2,%3};"                  \
        : "+f"((d)[0]), "+f"((d)[1]), "+f"((d)[2]), "+f"((d)[3])              \
        : "r"((a)[0]), "r"((a)[1]), "r"((a)[2]), "r"((a)[3]),                 \
          "r"(b0), "r"(b1))

#define CPA16(dst, src) \
    asm volatile("cp.async.ca.shared.global [%0], [%1], 16;" :: "r"(dst), "l"(src))
#define CPA_COMMIT() asm volatile("cp.async.commit_group;" ::: "memory")
#define CPA_WAIT(n)  asm volatile("cp.async.wait_group %0;" :: "n"(n) : "memory")

// smem: bias[128] | c[64][32] | 2 A slots | 2 W slots
#define OFF_BIAS 0
#define OFF_C    512
#define OFF_A    8704
#define OFF_W    78336                    // 8704 + 2*34816
#define SMEM_DYN 217600                   // 78336 + 2*69632

__global__ void zero_hb() {
    int i = blockIdx.x * 1024 + threadIdx.x;      // grid 512 -> 524288
    g_hb_hi[i] = __float2bfloat16(0.f);
    g_hb_lo[i] = __float2bfloat16(0.f);
}

__global__ void prep_x(const float* __restrict__ x) {
    size_t idx = (size_t)blockIdx.x * 1024 + threadIdx.x;   // 2^24
    int c  = (int)(idx & 127);
    int b  = (int)((idx >> 7) & 63);
    int ck = (int)((idx >> 13) & 7);
    int t  = (int)(idx >> 16);
    float v = x[((size_t)b * Tlen + t) * 1024 + ck * 128 + c];
    __nv_bfloat16 h = __float2bfloat16(v);
    size_t dst = (((size_t)(t * 8 + ck)) * 64 + b) * 128 + c;
    g_xb_hi[dst] = h;
    g_xb_lo[dst] = __float2bfloat16(v - __bfloat162float(h));
}

__global__ void prep_weights(const float* __restrict__ Wih,
                             const float* __restrict__ Whh) {
    size_t idx = (size_t)blockIdx.x * 1024 + threadIdx.x;   // 2^25
    int c  = (int)(idx & 127);
    int n  = (int)((idx >> 7) & 127);
    int ck = (int)((idx >> 14) & 15);
    int nb = (int)((idx >> 18) & 31);
    int l  = (int)(idx >> 23);
    int gate = n >> 5, hid = nb * 32 + (n & 31);
    int kk = ck * 128 + c;
    size_t grow = (size_t)l * 4096 * 1024 + (size_t)(gate * 1024 + hid) * 1024;
    float v = (kk < 1024) ? Wih[grow + kk] : Whh[grow + kk - 1024];
    __nv_bfloat16 h = __float2bfloat16(v);
    size_t e = ((((size_t)l * 32 + nb) * 16) + ck) * 16384 + (size_t)n * 128 + c;
    g_Whi[e] = h;
    g_Wlo[e] = __float2bfloat16(v - __bfloat162float(h));
}

__global__ __launch_bounds__(NTHR, 1) void lstm_persistent(
    const float* __restrict__ bih, const float* __restrict__ bhh)
{
    extern __shared__ char sm[];
    const uint32_t sbase = smem_u32(sm);

    const int tid  = threadIdx.x;
    const int wid  = tid >> 5;
    const int lane = tid & 31;
    const int bx   = blockIdx.x;
    const int L    = bx >> 5;            // this block's layer
    const int nb   = bx & 31;
    const int n0   = nb * 32;            // first hidden unit
    const int mt   = wid & 3;            // m-tile rows mt*16
    const int nt   = wid >> 2;           // n-tile cols nt*32

    if (tid < 128) {
        int gate = tid >> 5, hid = n0 + (tid & 31);
        int row = L * 4096 + gate * 1024 + hid;
        ((float*)(sm + OFF_BIAS))[tid] = bih[row] + bhh[row];
    }
    float* csm = (float*)(sm + OFF_C);   // [64][32]
    #pragma unroll
    for (int i = 0; i < 4; ++i)
        csm[i * NTHR + tid] = 0.f;
    __syncthreads();

    // ldmatrix per-lane offsets
    const uint32_t a_off = (uint32_t)(mt * 16 + (lane & 15)) * ASTR
                         + ((uint32_t)(lane >> 4) << 4);
    const uint32_t b_off0 = (uint32_t)(nt * 32 + (lane & 7) + ((lane >> 4) << 3)) * ASTR
                          + (((uint32_t)(lane >> 3) & 1u) << 4);
    const uint32_t b_off1 = b_off0 + 16u * ASTR;
    // cp.async dest offsets
    uint32_t wdo[4], ado[2];
    #pragma unroll
    for (int i = 0; i < 4; ++i) {
        int u = i * 512 + tid;
        wdo[i] = (uint32_t)(u >> 4) * ASTR + (uint32_t)(u & 15) * 16;
    }
    ado[0] = wdo[0]; ado[1] = wdo[1];

    const char* wBaseHi = (const char*)(g_Whi + (((size_t)L * 32 + nb) * 16) * 16384);
    const char* wBaseLo = (const char*)(g_Wlo + (((size_t)L * 32 + nb) * 16) * 16384);

    for (int s = 0; s < NSTEP; ++s) {
        const int t = s - L;
        if (0 <= t && t < Tlen) {
            const int par = t & 1;
            // A sources: chunks 0-7 = layer input, 8-15 = own h_{t-1}
            const char *blHi, *blLo;
            if (L == 0) {
                blHi = (const char*)(g_xb_hi + (size_t)t * 8 * 8192);
                blLo = (const char*)(g_xb_lo + (size_t)t * 8 * 8192);
            } else {
                size_t o = (size_t)((L - 1) * 2 + par) * 8 * 8192;
                blHi = (const char*)(g_hb_hi + o);
                blLo = (const char*)(g_hb_lo + o);
            }
            size_t oh = (size_t)(L * 2 + (par ^ 1)) * 8 * 8192;
            const char* bhHi = (const char*)(g_hb_hi + oh);
            const char* bhLo = (const char*)(g_hb_lo + oh);

            float c0[4][4] = {}, c1[4][4] = {}, c2[4][4] = {};

            #define ISSUE(ck, slot) do {                                      \
                const char* ah_ = ((ck) < 8) ? blHi + (size_t)(ck) * 16384    \
                                             : bhHi + (size_t)((ck) - 8) * 16384; \
                const char* al_ = ((ck) < 8) ? blLo + (size_t)(ck) * 16384    \
                                             : bhLo + (size_t)((ck) - 8) * 16384; \
                const char* wh_ = wBaseHi + (size_t)(ck) * 32768;             \
                const char* wl_ = wBaseLo + (size_t)(ck) * 32768;             \
                uint32_t aB = sbase + OFF_A + (uint32_t)(slot) * ASLOT;       \
                uint32_t wB = sbase + OFF_W + (uint32_t)(slot) * WSLOT;       \
                _Pragma("unroll")                                             \
                for (int i_ = 0; i_ < 4; ++i_) {                              \
                    CPA16(wB + wdo[i_], wh_ + (size_t)(i_ * 512 + tid) * 16); \
                    CPA16(wB + WHALF + wdo[i_],                               \
                          wl_ + (size_t)(i_ * 512 + tid) * 16);               \
                }                                                             \
                _Pragma("unroll")                                             \
                for (int i_ = 0; i_ < 2; ++i_) {                              \
                    CPA16(aB + ado[i_], ah_ + (size_t)(i_ * 512 + tid) * 16); \
                    CPA16(aB + AHALF + ado[i_],                               \
                          al_ + (size_t)(i_ * 512 + tid) * 16);               \
                }                                                             \
            } while (0)

            ISSUE(0, 0); CPA_COMMIT();

            for (int ck = 0; ck < NCHUNK; ++ck) {
                const int slot = ck & 1;
                __syncthreads();           // compute(ck-1) done -> slot^1 free
                if (ck + 1 < NCHUNK) {
                    ISSUE(ck + 1, slot ^ 1);
                    CPA_COMMIT();
                    CPA_WAIT(1);           // chunk ck landed
                } else {
                    CPA_WAIT(0);
                }
                __syncthreads();           // ck visible to all warps

                const uint32_t aH = sbase + OFF_A + (uint32_t)slot * ASLOT;
                const uint32_t aL = aH + AHALF;
                const uint32_t wH = sbase + OFF_W + (uint32_t)slot * WSLOT;
                const uint32_t wL = wH + WHALF;
                #pragma unroll
                for (int k = 0; k < 8; ++k) {
                    const uint32_t kb = (uint32_t)k * 32;
                    uint32_t ah[4], al[4], bh0[4], bh1[4], bl0[4], bl1[4];
                    LDSM4(ah,  aH + a_off + kb);
                    LDSM4(al,  aL + a_off + kb);
                    LDSM4(bh0, wH + b_off0 + kb);
                    LDSM4(bh1, wH + b_off1 + kb);
                    LDSM4(bl0, wL + b_off0 + kb);
                    LDSM4(bl1, wL + b_off1 + kb);
                    MMA(c0[0], ah, bh0[0], bh0[1]);
                    MMA(c0[1], ah, bh0[2], bh0[3]);
                    MMA(c0[2], ah, bh1[0], bh1[1]);
                    MMA(c0[3], ah, bh1[2], bh1[3]);
                    MMA(c1[0], al, bh0[0], bh0[1]);
                    MMA(c1[1], al, bh0[2], bh0[3]);
                    MMA(c1[2], al, bh1[0], bh1[1]);
                    MMA(c1[3], al, bh1[2], bh1[3]);
                    MMA(c2[0], ah, bl0[0], bl0[1]);
                    MMA(c2[1], ah, bl0[2], bl0[3]);
                    MMA(c2[2], ah, bl1[0], bl1[1]);
                    MMA(c2[3], ah, bl1[2], bl1[3]);
                }
            }
            #undef ISSUE

            // epilogue: Gs in A slot 0 (compute(15) used slot 1)
            float* Gs = (float*)(sm + OFF_A);   // [64][132]
            #pragma unroll
            for (int j = 0; j < 4; ++j) {
                int R = mt * 16 + (lane >> 2);
                int C = nt * 32 + j * 8 + (lane & 3) * 2;
                Gs[R * 132 + C]           = c0[j][0] + c1[j][0] + c2[j][0];
                Gs[R * 132 + C + 1]       = c0[j][1] + c1[j][1] + c2[j][1];
                Gs[(R + 8) * 132 + C]     = c0[j][2] + c1[j][2] + c2[j][2];
                Gs[(R + 8) * 132 + C + 1] = c0[j][3] + c1[j][3] + c2[j][3];
            }
            __syncthreads();

            {
                const float* bias = (const float*)(sm + OFF_BIAS);
                const int ckd = nb >> 2;
                #pragma unroll
                for (int q = 0; q < 4; ++q) {
                    int e = q * 512 + tid;          // 0..2047
                    int b = e >> 5, hl = e & 31;
                    float gi = Gs[b * 132 + hl]       + bias[hl];
                    float gf = Gs[b * 132 + 32 + hl]  + bias[32 + hl];
                    float gg = Gs[b * 132 + 64 + hl]  + bias[64 + hl];
                    float go = Gs[b * 132 + 96 + hl]  + bias[96 + hl];
                    float ig = sigf(gi), fg = sigf(gf), og = sigf(go);
                    float gt = tanhfast(gg);
                    float* cp_ = csm + b * 32 + hl;
                    float cn = fg * (*cp_) + ig * gt;
                    *cp_ = cn;
                    float hn = og * tanhfast(cn);
                    __nv_bfloat16 hh = __float2bfloat16(hn);
                    __nv_bfloat16 hlw = __float2bfloat16(hn - __bfloat162float(hh));
                    int coltile = (nb & 3) * 32 + hl;
                    size_t off = ((((size_t)(L * 2 + par) * 8 + ckd) * 64 + b) * 128)
                               + coltile;
                    g_hb_hi[off] = hh;
                    g_hb_lo[off] = hlw;
                    if (t == Tlen - 1 && L == Lnum - 1)
                        g_hfin[(size_t)b * Hdim + n0 + hl] = hn;
                }
            }
        }
        grid_sync();
    }
}

__global__ void fc_kernel(const float* __restrict__ Wfc,
                          const float* __restrict__ bfc,
                          float* __restrict__ out)
{
    const float* h = g_hfin;
    int warp = (blockIdx.x * blockDim.x + threadIdx.x) >> 5;
    int lane = threadIdx.x & 31;
    int b = warp >> 9;
    int o = warp & (Odim - 1);
    const float4* hv = (const float4*)(h   + (size_t)b * Hdim);
    const float4* wv = (const float4*)(Wfc + (size_t)o * Hdim);
    float s = 0.f;
    #pragma unroll
    for (int it = 0; it < 8; ++it) {
        float4 a = hv[it * 32 + lane];
        float4 w = wv[it * 32 + lane];
        s += a.x * w.x + a.y * w.y + a.z * w.z + a.w * w.w;
    }
    #pragma unroll
    for (int off = 16; off; off >>= 1)
        s += __shfl_xor_sync(0xffffffffu, s, off);
    if (lane == 0)
        out[(size_t)b * Odim + o] = s + bfc[o];
}

extern "C" void kernel_launch(void* const* d_in, const int* in_sizes, int n_in,
                              void* d_out, int out_size)
{
    const float* x   = (const float*)d_in[0];
    const float* Wih = (const float*)d_in[1];
    const float* Whh = (const float*)d_in[2];
    const float* bih = (const float*)d_in[3];
    const float* bhh = (const float*)d_in[4];
    const float* Wfc = (const float*)d_in[5];
    const float* bfc = (const float*)d_in[6];
    float* out = (float*)d_out;

    cudaFuncSetAttribute(lstm_persistent,
                         cudaFuncAttributeMaxDynamicSharedMemorySize, SMEM_DYN);

    zero_hb<<<512, 1024>>>();
    prep_x<<<16384, 1024>>>(x);
    prep_weights<<<32768, 1024>>>(Wih, Whh);
    lstm_persistent<<<NBLK, NTHR, SMEM_DYN>>>(bih, bhh);
    fc_kernel<<<(Bsz * Odim) / 8, 256>>>(Wfc, bfc, out);
}

// round 12
// speedup vs baseline: 3.7199x; 1.0370x over previous
#include <cuda_runtime.h>
#include <cuda_bf16.h>
#include <stdint.h>
#include <math.h>

#define Bsz  64
#define Tlen 256
#define Hdim 1024
#define Lnum 4
#define Odim 512
#define NBLK 128
#define NTHR 512
#define NCHUNK 16
#define NSTEP (Tlen + Lnum - 1)    // 259 wavefront steps
#define ASTR 272                   // smem row pitch bytes
#define AHALF 17408u               // 64 rows * 272
#define ASLOT 34816u               // A hi+lo
#define WHALF 34816u               // 128 rows * 272
#define WSLOT 69632u               // W hi+lo

// ---- persistent device state ----
__device__ __nv_bfloat16 g_Whi[(size_t)Lnum * 32 * 16 * 128 * 128];  // 64 MB
__device__ __nv_bfloat16 g_Wlo[(size_t)Lnum * 32 * 16 * 128 * 128];  // 64 MB
__device__ __nv_bfloat16 g_xb_hi[(size_t)Tlen * 8 * 64 * 128];       // 32 MB
__device__ __nv_bfloat16 g_xb_lo[(size_t)Tlen * 8 * 64 * 128];       // 32 MB
__device__ __nv_bfloat16 g_hb_hi[Lnum * 2 * 8 * 64 * 128];           // 1 MB
__device__ __nv_bfloat16 g_hb_lo[Lnum * 2 * 8 * 64 * 128];           // 1 MB
__device__ float g_hfin[Bsz * Hdim];

__device__ volatile unsigned g_gen = 0;
__device__ unsigned g_count = 0;

__device__ __forceinline__ void grid_sync() {
    __syncthreads();
    if (threadIdx.x == 0) {
        __threadfence();
        unsigned my = g_gen;
        if (atomicAdd(&g_count, 1u) == NBLK - 1) {
            g_count = 0; __threadfence(); g_gen = my + 1;
        } else {
            while (g_gen == my) { __nanosleep(20); }
        }
        __threadfence();
    }
    __syncthreads();
}

__device__ __forceinline__ uint32_t smem_u32(const void* p) {
    uint32_t a;
    asm("{ .reg .u64 t; cvta.to.shared.u64 t, %1; cvt.u32.u64 %0, t; }"
        : "=r"(a) : "l"(p));
    return a;
}
__device__ __forceinline__ float ex2f(float x) {
    float r; asm("ex2.approx.f32 %0, %1;" : "=f"(r) : "f"(x)); return r;
}
__device__ __forceinline__ float rcpf(float x) {
    float r; asm("rcp.approx.f32 %0, %1;" : "=f"(r) : "f"(x)); return r;
}
__device__ __forceinline__ float sigf(float x) {
    return rcpf(1.0f + ex2f(-1.4426950408889634f * x));
}
__device__ __forceinline__ float tanhfast(float x) {
    float e = ex2f(2.8853900817779268f * x);
    return 1.0f - 2.0f * rcpf(e + 1.0f);
}

#define LDSM4(r, a)                                                           \
    asm volatile("ldmatrix.sync.aligned.m8n8.x4.shared.b16 {%0,%1,%2,%3}, [%4];" \
        : "=r"((r)[0]), "=r"((r)[1]), "=r"((r)[2]), "=r"((r)[3]) : "r"(a))

#define MMA(d, a, b0, b1)                                                     \
    asm volatile("mma.sync.aligned.m16n8k16.row.col.f32.bf16.bf16.f32 "       \
        "{%0,%1,%2,%3},{%4,%5,%6,%7},{%8,%9},{%0,%1,%2,%3};"                  \
        : "+f"((d)[0]), "+f"((d)[1]), "+f"((d)[2]), "+f"((d)[3])              \
        : "r"((a)[0]), "r"((a)[1]), "r"((a)[2]), "r"((a)[3]),                 \
          "r"(b0), "r"(b1))

#define CPA16(dst, src) \
    asm volatile("cp.async.ca.shared.global [%0], [%1], 16;" :: "r"(dst), "l"(src))
#define CPA_COMMIT() asm volatile("cp.async.commit_group;" ::: "memory")
#define CPA_WAIT(n)  asm volatile("cp.async.wait_group %0;" :: "n"(n) : "memory")

// smem: bias[128] | c[64][32] | 2 A slots | 2 W slots
#define OFF_BIAS 0
#define OFF_C    512
#define OFF_A    8704
#define OFF_W    78336                    // 8704 + 2*34816
#define SMEM_DYN 217600                   // 78336 + 2*69632

__global__ void zero_hb() {
    int i = blockIdx.x * 1024 + threadIdx.x;      // grid 512
    g_hb_hi[i] = __float2bfloat16(0.f);
    g_hb_lo[i] = __float2bfloat16(0.f);
}

__global__ void prep_x(const float* __restrict__ x) {
    size_t idx = (size_t)blockIdx.x * 1024 + threadIdx.x;   // 2^24
    int c  = (int)(idx & 127);
    int b  = (int)((idx >> 7) & 63);
    int ck = (int)((idx >> 13) & 7);
    int t  = (int)(idx >> 16);
    float v = x[((size_t)b * Tlen + t) * 1024 + ck * 128 + c];
    __nv_bfloat16 h = __float2bfloat16(v);
    size_t dst = (((size_t)(t * 8 + ck)) * 64 + b) * 128 + c;
    g_xb_hi[dst] = h;
    g_xb_lo[dst] = __float2bfloat16(v - __bfloat162float(h));
}

__global__ void prep_weights(const float* __restrict__ Wih,
                             const float* __restrict__ Whh) {
    size_t idx = (size_t)blockIdx.x * 1024 + threadIdx.x;   // 2^25
    int c  = (int)(idx & 127);
    int n  = (int)((idx >> 7) & 127);
    int ck = (int)((idx >> 14) & 15);
    int nb = (int)((idx >> 18) & 31);
    int l  = (int)(idx >> 23);
    int gate = n >> 5, hid = nb * 32 + (n & 31);
    int kk = ck * 128 + c;
    size_t grow = (size_t)l * 4096 * 1024 + (size_t)(gate * 1024 + hid) * 1024;
    float v = (kk < 1024) ? Wih[grow + kk] : Whh[grow + kk - 1024];
    __nv_bfloat16 h = __float2bfloat16(v);
    size_t e = ((((size_t)l * 32 + nb) * 16) + ck) * 16384 + (size_t)n * 128 + c;
    g_Whi[e] = h;
    g_Wlo[e] = __float2bfloat16(v - __bfloat162float(h));
}

__global__ __launch_bounds__(NTHR, 1) void lstm_persistent(
    const float* __restrict__ bih, const float* __restrict__ bhh)
{
    extern __shared__ char sm[];
    const uint32_t sbase = smem_u32(sm);

    const int tid  = threadIdx.x;
    const int wid  = tid >> 5;
    const int lane = tid & 31;
    const int bx   = blockIdx.x;
    const int L    = bx >> 5;            // this block's layer
    const int nb   = bx & 31;
    const int n0   = nb * 32;            // first hidden unit
    // warp tiling: m32 x n32, 2-way k-split
    const int mt = wid & 1;              // m rows mt*32..+31
    const int nt = (wid >> 1) & 3;       // n cols nt*32..+31
    const int kg = wid >> 3;             // k-steps kg*4..+3

    if (tid < 128) {
        int gate = tid >> 5, hid = n0 + (tid & 31);
        int row = L * 4096 + gate * 1024 + hid;
        ((float*)(sm + OFF_BIAS))[tid] = bih[row] + bhh[row];
    }
    float* csm = (float*)(sm + OFF_C);   // [64][32]
    #pragma unroll
    for (int i = 0; i < 4; ++i)
        csm[i * NTHR + tid] = 0.f;
    __syncthreads();

    // ldmatrix per-lane offsets
    const uint32_t a_off0 = (uint32_t)(mt * 32 + (lane & 15)) * ASTR
                          + ((uint32_t)(lane >> 4) << 4);
    const uint32_t a_off1 = a_off0 + 16u * ASTR;
    const uint32_t b_off0 = (uint32_t)(nt * 32 + (lane & 7) + ((lane >> 4) << 3)) * ASTR
                          + (((uint32_t)(lane >> 3) & 1u) << 4);
    const uint32_t b_off1 = b_off0 + 16u * ASTR;
    // cp.async dest offsets
    uint32_t wdo[4], ado[2];
    #pragma unroll
    for (int i = 0; i < 4; ++i) {
        int u = i * 512 + tid;
        wdo[i] = (uint32_t)(u >> 4) * ASTR + (uint32_t)(u & 15) * 16;
    }
    ado[0] = wdo[0]; ado[1] = wdo[1];
    const uint32_t kb0 = (uint32_t)kg * 128;   // 4 k-steps * 32B

    const char* wBaseHi = (const char*)(g_Whi + (((size_t)L * 32 + nb) * 16) * 16384);
    const char* wBaseLo = (const char*)(g_Wlo + (((size_t)L * 32 + nb) * 16) * 16384);

    for (int s = 0; s < NSTEP; ++s) {
        const int t = s - L;
        if (0 <= t && t < Tlen) {
            const int par = t & 1;
            const char *blHi, *blLo;
            if (L == 0) {
                blHi = (const char*)(g_xb_hi + (size_t)t * 8 * 8192);
                blLo = (const char*)(g_xb_lo + (size_t)t * 8 * 8192);
            } else {
                size_t o = (size_t)((L - 1) * 2 + par) * 8 * 8192;
                blHi = (const char*)(g_hb_hi + o);
                blLo = (const char*)(g_hb_lo + o);
            }
            size_t oh = (size_t)(L * 2 + (par ^ 1)) * 8 * 8192;
            const char* bhHi = (const char*)(g_hb_hi + oh);
            const char* bhLo = (const char*)(g_hb_lo + oh);

            // merged accumulators: all 3 precision passes into one set
            float acc[2][4][4] = {};

            #define ISSUE(ck, slot) do {                                      \
                const char* ah_ = ((ck) < 8) ? blHi + (size_t)(ck) * 16384    \
                                             : bhHi + (size_t)((ck) - 8) * 16384; \
                const char* al_ = ((ck) < 8) ? blLo + (size_t)(ck) * 16384    \
                                             : bhLo + (size_t)((ck) - 8) * 16384; \
                const char* wh_ = wBaseHi + (size_t)(ck) * 32768;             \
                const char* wl_ = wBaseLo + (size_t)(ck) * 32768;             \
                uint32_t aB = sbase + OFF_A + (uint32_t)(slot) * ASLOT;       \
                uint32_t wB = sbase + OFF_W + (uint32_t)(slot) * WSLOT;       \
                _Pragma("unroll")                                             \
                for (int i_ = 0; i_ < 4; ++i_) {                              \
                    CPA16(wB + wdo[i_], wh_ + (size_t)(i_ * 512 + tid) * 16); \
                    CPA16(wB + WHALF + wdo[i_],                               \
                          wl_ + (size_t)(i_ * 512 + tid) * 16);               \
                }                                                             \
                _Pragma("unroll")                                             \
                for (int i_ = 0; i_ < 2; ++i_) {                              \
                    CPA16(aB + ado[i_], ah_ + (size_t)(i_ * 512 + tid) * 16); \
                    CPA16(aB + AHALF + ado[i_],                               \
                          al_ + (size_t)(i_ * 512 + tid) * 16);               \
                }                                                             \
            } while (0)

            ISSUE(0, 0); CPA_COMMIT();

            for (int ck = 0; ck < NCHUNK; ++ck) {
                const int slot = ck & 1;
                __syncthreads();           // compute(ck-1) done -> slot^1 free
                if (ck + 1 < NCHUNK) {
                    ISSUE(ck + 1, slot ^ 1);
                    CPA_COMMIT();
                    CPA_WAIT(1);           // chunk ck landed
                } else {
                    CPA_WAIT(0);
                }
                __syncthreads();           // ck visible to all warps

                const uint32_t aH = sbase + OFF_A + (uint32_t)slot * ASLOT;
                const uint32_t aL = aH + AHALF;
                const uint32_t wH = sbase + OFF_W + (uint32_t)slot * WSLOT;
                const uint32_t wL = wH + WHALF;
                #pragma unroll
                for (int kk = 0; kk < 4; ++kk) {
                    const uint32_t kb = kb0 + (uint32_t)kk * 32;
                    uint32_t ah0[4], ah1[4], al0[4], al1[4];
                    uint32_t bh0[4], bh1[4], bl0[4], bl1[4];
                    LDSM4(ah0, aH + a_off0 + kb);
                    LDSM4(ah1, aH + a_off1 + kb);
                    LDSM4(al0, aL + a_off0 + kb);
                    LDSM4(al1, aL + a_off1 + kb);
                    LDSM4(bh0, wH + b_off0 + kb);
                    LDSM4(bh1, wH + b_off1 + kb);
                    LDSM4(bl0, wL + b_off0 + kb);
                    LDSM4(bl1, wL + b_off1 + kb);
                    // pass hi*hi (8 independent tiles)
                    MMA(acc[0][0], ah0, bh0[0], bh0[1]);
                    MMA(acc[0][1], ah0, bh0[2], bh0[3]);
                    MMA(acc[0][2], ah0, bh1[0], bh1[1]);
                    MMA(acc[0][3], ah0, bh1[2], bh1[3]);
                    MMA(acc[1][0], ah1, bh0[0], bh0[1]);
                    MMA(acc[1][1], ah1, bh0[2], bh0[3]);
                    MMA(acc[1][2], ah1, bh1[0], bh1[1]);
                    MMA(acc[1][3], ah1, bh1[2], bh1[3]);
                    // pass lo*hi
                    MMA(acc[0][0], al0, bh0[0], bh0[1]);
                    MMA(acc[0][1], al0, bh0[2], bh0[3]);
                    MMA(acc[0][2], al0, bh1[0], bh1[1]);
                    MMA(acc[0][3], al0, bh1[2], bh1[3]);
                    MMA(acc[1][0], al1, bh0[0], bh0[1]);
                    MMA(acc[1][1], al1, bh0[2], bh0[3]);
                    MMA(acc[1][2], al1, bh1[0], bh1[1]);
                    MMA(acc[1][3], al1, bh1[2], bh1[3]);
                    // pass hi*lo
                    MMA(acc[0][0], ah0, bl0[0], bl0[1]);
                    MMA(acc[0][1], ah0, bl0[2], bl0[3]);
                    MMA(acc[0][2], ah0, bl1[0], bl1[1]);
                    MMA(acc[0][3], ah0, bl1[2], bl1[3]);
                    MMA(acc[1][0], ah1, bl0[0], bl0[1]);
                    MMA(acc[1][1], ah1, bl0[2], bl0[3]);
                    MMA(acc[1][2], ah1, bl1[0], bl1[1]);
                    MMA(acc[1][3], ah1, bl1[2], bl1[3]);
                }
            }
            #undef ISSUE

            __syncthreads();   // ALL warps done reading slots before Gs reuse

            // partial gates per k-group: Gs[2][64][132] = 67584 B (fits A region)
            float* Gs = (float*)(sm + OFF_A);
            #pragma unroll
            for (int mi = 0; mi < 2; ++mi) {
                #pragma unroll
                for (int ni = 0; ni < 4; ++ni) {
                    int R = mt * 32 + mi * 16 + (lane >> 2);
                    int C = nt * 32 + ni * 8 + (lane & 3) * 2;
                    int base = (kg * 64 + R) * 132 + C;
                    Gs[base]           = acc[mi][ni][0];
                    Gs[base + 1]       = acc[mi][ni][1];
                    Gs[base + 8 * 132]     = acc[mi][ni][2];
                    Gs[base + 8 * 132 + 1] = acc[mi][ni][3];
                }
            }
            __syncthreads();

            {
                const float* bias = (const float*)(sm + OFF_BIAS);
                const int ckd = nb >> 2;
                #pragma unroll
                for (int q = 0; q < 4; ++q) {
                    int e = q * 512 + tid;          // 0..2047
                    int b = e >> 5, hl = e & 31;
                    float gi = Gs[b * 132 + hl]       + Gs[(64 + b) * 132 + hl]
                             + bias[hl];
                    float gf = Gs[b * 132 + 32 + hl]  + Gs[(64 + b) * 132 + 32 + hl]
                             + bias[32 + hl];
                    float gg = Gs[b * 132 + 64 + hl]  + Gs[(64 + b) * 132 + 64 + hl]
                             + bias[64 + hl];
                    float go = Gs[b * 132 + 96 + hl]  + Gs[(64 + b) * 132 + 96 + hl]
                             + bias[96 + hl];
                    float ig = sigf(gi), fg = sigf(gf), og = sigf(go);
                    float gt = tanhfast(gg);
                    float* cp_ = csm + b * 32 + hl;
                    float cn = fg * (*cp_) + ig * gt;
                    *cp_ = cn;
                    float hn = og * tanhfast(cn);
                    __nv_bfloat16 hh = __float2bfloat16(hn);
                    __nv_bfloat16 hlw = __float2bfloat16(hn - __bfloat162float(hh));
                    int coltile = (nb & 3) * 32 + hl;
                    size_t off = ((((size_t)(L * 2 + par) * 8 + ckd) * 64 + b) * 128)
                               + coltile;
                    g_hb_hi[off] = hh;
                    g_hb_lo[off] = hlw;
                    if (t == Tlen - 1 && L == Lnum - 1)
                        g_hfin[(size_t)b * Hdim + n0 + hl] = hn;
                }
            }
        }
        grid_sync();
    }
}

__global__ void fc_kernel(const float* __restrict__ Wfc,
                          const float* __restrict__ bfc,
                          float* __restrict__ out)
{
    const float* h = g_hfin;
    int warp = (blockIdx.x * blockDim.x + threadIdx.x) >> 5;
    int lane = threadIdx.x & 31;
    int b = warp >> 9;
    int o = warp & (Odim - 1);
    const float4* hv = (const float4*)(h   + (size_t)b * Hdim);
    const float4* wv = (const float4*)(Wfc + (size_t)o * Hdim);
    float s = 0.f;
    #pragma unroll
    for (int it = 0; it < 8; ++it) {
        float4 a = hv[it * 32 + lane];
        float4 w = wv[it * 32 + lane];
        s += a.x * w.x + a.y * w.y + a.z * w.z + a.w * w.w;
    }
    #pragma unroll
    for (int off = 16; off; off >>= 1)
        s += __shfl_xor_sync(0xffffffffu, s, off);
    if (lane == 0)
        out[(size_t)b * Odim + o] = s + bfc[o];
}

extern "C" void kernel_launch(void* const* d_in, const int* in_sizes, int n_in,
                              void* d_out, int out_size)
{
    const float* x   = (const float*)d_in[0];
    const float* Wih = (const float*)d_in[1];
    const float* Whh = (const float*)d_in[2];
    const float* bih = (const float*)d_in[3];
    const float* bhh = (const float*)d_in[4];
    const float* Wfc = (const float*)d_in[5];
    const float* bfc = (const float*)d_in[6];
    float* out = (float*)d_out;

    cudaFuncSetAttribute(lstm_persistent,
                         cudaFuncAttributeMaxDynamicSharedMemorySize, SMEM_DYN);

    zero_hb<<<512, 1024>>>();
    prep_x<<<16384, 1024>>>(x);
    prep_weights<<<32768, 1024>>>(Wih, Whh);
    lstm_persistent<<<NBLK, NTHR, SMEM_DYN>>>(bih, bhh);
    fc_kernel<<<(Bsz * Odim) / 8, 256>>>(Wfc, bfc, out);
}